// round 12
// baseline (speedup 1.0000x reference)
#include <cuda_runtime.h>
#include <cuda_fp16.h>
#include <mma.h>
#include <cstdint>

using namespace nvcuda;

// Problem constants (fixed by the dataset)
#define NN 40000
#define EE 400000
#define GG 256
#define DIN 256
#define HH 4

#define MPAD 40064   // 313 * 128, padded rows for unguarded stores

// ---------------- scratch (static device globals; no allocation) ----------------
__device__ __half g_hlinh[(size_t)MPAD * 512];  // GEMM output (half), current layer
__device__ __half g_xh[(size_t)NN * DIN];       // x converted to half
__device__ __half g_w1h[DIN * 512];
__device__ __half g_w2h[128 * 512];
__device__ __half g_w3h[128 * 128];
__device__ __half g_f1h[(size_t)NN * 128];      // layer1 out (half)
__device__ __half g_f2h[(size_t)NN * 128];      // layer2 out (half)
__device__ float  g_f3[(size_t)NN * 128];       // layer3 out (float, feeds pool)
__device__ float  g_ssrc[NN * HH];
__device__ float  g_sdst[NN * HH];
__device__ int    g_rowptr[NN + 1];
__device__ int    g_cursor[NN];
__device__ int    g_deg[NN];
__device__ int    g_esrc[EE];
__device__ int    g_bsums[64];
__device__ float  g_tot[GG * 128];
__device__ float  g_cnt[GG];

// ---------------- utility kernels ----------------
__global__ void kzero_i(int* p, int n) {
    int i = blockIdx.x * blockDim.x + threadIdx.x;
    if (i < n) p[i] = 0;
}
__global__ void kzero_pool(float* tot, float* cnt) {
    int i = blockIdx.x * blockDim.x + threadIdx.x;
    if (i < GG * 128) tot[i] = 0.f;
    if (i < GG) cnt[i] = 0.f;
}

// convert fp32 array to half, 8 elements per thread (n % 8 == 0)
__global__ void conv_half(const float* __restrict__ in, __half* __restrict__ out, int n8) {
    int i = blockIdx.x * blockDim.x + threadIdx.x;
    if (i < n8) {
        float4 a = ((const float4*)in)[2 * i];
        float4 b = ((const float4*)in)[2 * i + 1];
        __half2 h[4];
        h[0] = __floats2half2_rn(a.x, a.y);
        h[1] = __floats2half2_rn(a.z, a.w);
        h[2] = __floats2half2_rn(b.x, b.y);
        h[3] = __floats2half2_rn(b.z, b.w);
        ((uint4*)out)[i] = *(uint4*)h;
    }
}

__global__ void hist_k(const int* __restrict__ dst, int* __restrict__ deg) {
    int e = blockIdx.x * blockDim.x + threadIdx.x;
    if (e < EE) atomicAdd(&deg[dst[e]], 1);
}

__global__ void scan_block(const int* __restrict__ deg, int* __restrict__ rowptr,
                           int* __restrict__ bsums, int n) {
    __shared__ int tmp[1024];
    int i = blockIdx.x * 1024 + threadIdx.x;
    int v = (i < n) ? deg[i] : 0;
    tmp[threadIdx.x] = v;
    __syncthreads();
    for (int off = 1; off < 1024; off <<= 1) {
        int t = (threadIdx.x >= off) ? tmp[threadIdx.x - off] : 0;
        __syncthreads();
        tmp[threadIdx.x] += t;
        __syncthreads();
    }
    if (i < n) rowptr[i] = tmp[threadIdx.x] - v;  // exclusive
    if (threadIdx.x == 1023) bsums[blockIdx.x] = tmp[1023];
}

__global__ void scan_sums(int* bsums, int nb) {
    if (threadIdx.x == 0 && blockIdx.x == 0) {
        int run = 0;
        for (int b = 0; b < nb; b++) { int v = bsums[b]; bsums[b] = run; run += v; }
    }
}

__global__ void scan_add(int* __restrict__ rowptr, int* __restrict__ cursor,
                         const int* __restrict__ bsums, int n) {
    int i = blockIdx.x * blockDim.x + threadIdx.x;
    if (i < n) {
        int v = rowptr[i] + bsums[i >> 10];
        rowptr[i] = v;
        cursor[i] = v;
    }
    if (i == 0) rowptr[n] = EE;
}

__global__ void scatter_k(const int* __restrict__ src, const int* __restrict__ dst,
                          int* __restrict__ cursor, int* __restrict__ esrc) {
    int e = blockIdx.x * blockDim.x + threadIdx.x;
    if (e < EE) {
        int pos = atomicAdd(&cursor[dst[e]], 1);
        esrc[pos] = src[e];
    }
}

// ---------------- FP16 tensor-core GEMM + fused attention-score epilogue ----------
#define GBM 128
#define GBN 128
#define GBK 32
#define ALD 40     // A smem row stride (halfs)
#define BLD 136    // B smem row stride (halfs)
#define AB_BYTES (2 * GBM * ALD * 2 + 2 * GBK * BLD * 2)   // 37888
#define CS_LD 68   // epilogue float staging stride

__global__ __launch_bounds__(256) void gemm_h(int M, int K, int Nc,
    const __half* __restrict__ A, const __half* __restrict__ B, __half* __restrict__ C,
    int heads, const float* __restrict__ asrc, const float* __restrict__ adst,
    float* __restrict__ ssrc, float* __restrict__ sdst)
{
    __shared__ __align__(16) char smem_raw[AB_BYTES];   // reused by epilogue
    __half* Ah = (__half*)smem_raw;                     // [2][GBM*ALD]
    __half* Bh = Ah + 2 * GBM * ALD;                    // [2][GBK*BLD]

    const int tid = threadIdx.x;
    const int warpId = tid >> 5;
    const int warpM = warpId & 3;
    const int warpN = warpId >> 2;
    const int head = blockIdx.x;
    const int blockM = blockIdx.y * GBM;
    const int blockN = head * GBN;

    const unsigned int sA = (unsigned int)__cvta_generic_to_shared(Ah);
    const unsigned int sB = (unsigned int)__cvta_generic_to_shared(Bh);

    wmma::fragment<wmma::accumulator, 16, 16, 16, float> acc[2][4];
#pragma unroll
    for (int i = 0; i < 2; i++)
#pragma unroll
        for (int j = 0; j < 4; j++) wmma::fill_fragment(acc[i][j], 0.f);

    const int nsteps = K / GBK;

    auto stage = [&](int buf, int k0) {
#pragma unroll
        for (int q = 0; q < 2; q++) {
            int c = tid + q * 256;
            int ar = c >> 2, ac = (c & 3) * 8;
            int gr = blockM + ar;
            const __half* gpA = A + (size_t)gr * K + k0 + ac;
            unsigned int saA = sA + (unsigned int)(buf * GBM * ALD + ar * ALD + ac) * 2u;
            int sz = (gr < M) ? 16 : 0;
            asm volatile("cp.async.cg.shared.global [%0], [%1], 16, %2;\n"
                         :: "r"(saA), "l"(gpA), "r"(sz));
            int br = c >> 4, bc = (c & 15) * 8;
            const __half* gpB = B + (size_t)(k0 + br) * Nc + blockN + bc;
            unsigned int saB = sB + (unsigned int)(buf * GBK * BLD + br * BLD + bc) * 2u;
            asm volatile("cp.async.cg.shared.global [%0], [%1], 16;\n"
                         :: "r"(saB), "l"(gpB));
        }
        asm volatile("cp.async.commit_group;\n");
    };

    stage(0, 0);

    for (int s = 0; s < nsteps; s++) {
        const int p = s & 1;
        if (s + 1 < nsteps) {
            stage(1 - p, (s + 1) * GBK);
            asm volatile("cp.async.wait_group 1;\n");
        } else {
            asm volatile("cp.async.wait_group 0;\n");
        }
        __syncthreads();

        const __half* ap = Ah + p * GBM * ALD;
        const __half* bp = Bh + p * GBK * BLD;
#pragma unroll
        for (int kk = 0; kk < GBK; kk += 16) {
            wmma::fragment<wmma::matrix_a, 16, 16, 16, __half, wmma::row_major> af[2];
            wmma::fragment<wmma::matrix_b, 16, 16, 16, __half, wmma::row_major> bf[4];
#pragma unroll
            for (int i = 0; i < 2; i++)
                wmma::load_matrix_sync(af[i], ap + (warpM * 32 + i * 16) * ALD + kk, ALD);
#pragma unroll
            for (int j = 0; j < 4; j++)
                wmma::load_matrix_sync(bf[j], bp + kk * BLD + warpN * 64 + j * 16, BLD);
#pragma unroll
            for (int i = 0; i < 2; i++)
#pragma unroll
                for (int j = 0; j < 4; j++)
                    wmma::mma_sync(acc[i][j], af[i], bf[j], acc[i][j]);
        }
        __syncthreads();
    }

    // fused epilogue: acc -> smem(fp32) -> half C + attention dots
    float* Cs = (float*)smem_raw;            // [128][CS_LD]
    const float* asrc_h = asrc + head * 128;
    const float* adst_h = adst + head * 128;
    const int row = tid >> 1;
    const int cseg = (tid & 1) * 32;
    float ds = 0.f, dd = 0.f;

#pragma unroll
    for (int p = 0; p < 2; p++) {
        if (warpN == p) {
#pragma unroll
            for (int i = 0; i < 2; i++)
#pragma unroll
                for (int j = 0; j < 4; j++)
                    wmma::store_matrix_sync(Cs + (warpM * 32 + i * 16) * CS_LD + j * 16,
                                            acc[i][j], CS_LD, wmma::mem_row_major);
        }
        __syncthreads();

        const float* crow = Cs + row * CS_LD + cseg;
        __half2 hbuf[16];
        int colbase = p * 64 + cseg;
#pragma unroll
        for (int k = 0; k < 32; k += 2) {
            float a0 = crow[k], a1 = crow[k + 1];
            hbuf[k >> 1] = __floats2half2_rn(a0, a1);
            ds += a0 * asrc_h[colbase + k] + a1 * asrc_h[colbase + k + 1];
            dd += a0 * adst_h[colbase + k] + a1 * adst_h[colbase + k + 1];
        }
        uint4* dstp = (uint4*)(C + (size_t)(blockM + row) * Nc + blockN + colbase);
        const uint4* srcv = (const uint4*)hbuf;
        dstp[0] = srcv[0]; dstp[1] = srcv[1]; dstp[2] = srcv[2]; dstp[3] = srcv[3];
        __syncthreads();
    }

    ds += __shfl_xor_sync(0xffffffffu, ds, 1);
    dd += __shfl_xor_sync(0xffffffffu, dd, 1);
    int gr = blockM + row;
    if ((tid & 1) == 0 && gr < M) {
        ssrc[gr * heads + head] = ds;
        sdst[gr * heads + head] = dd;
    }
}

// ---------------- per-dst aggregation, 2 warps per head ----------------
// Block = HEADS*64 threads (2*HEADS warps). warp w: head = w % HEADS,
// sub = w / HEADS (0/1). Each sub processes edges j = sub, sub+2, ...
// partial (acc, z) combined via smem; per-head scale uses combined z.
template <int HEADS, bool ELUBN>
__global__ void gat_agg(const __half* __restrict__ hlin,
                        const float* __restrict__ ssrc, const float* __restrict__ sdst,
                        const int* __restrict__ rowptr, const int* __restrict__ esrc,
                        const float* __restrict__ bias,
                        const float* __restrict__ gam, const float* __restrict__ bet,
                        const float* __restrict__ rm, const float* __restrict__ rv,
                        __half* __restrict__ outh, float* __restrict__ outf)
{
    const int NW = 2 * HEADS;
    const int T = NW * 32;
    const int n = blockIdx.x;
    const int tid = threadIdx.x;
    const int warp = tid >> 5;
    const int head = warp % HEADS;
    const int sub = warp / HEADS;
    const int lane = tid & 31;
    const int start = rowptr[n];
    const int deg = rowptr[n + 1] - start;   // real in-edges; +1 implicit self loop

    float sd[HEADS];
#pragma unroll
    for (int h = 0; h < HEADS; h++) sd[h] = sdst[n * HEADS + h];

    // pass 1: per-head max over edges (incl. self loop at index deg)
    float ml[HEADS];
#pragma unroll
    for (int h = 0; h < HEADS; h++) ml[h] = -1e30f;
    for (int i = tid; i <= deg; i += T) {
        int s = (i == deg) ? n : esrc[start + i];
#pragma unroll
        for (int h = 0; h < HEADS; h++) {
            float e = ssrc[s * HEADS + h] + sd[h];
            e = e > 0.f ? e : 0.2f * e;
            ml[h] = fmaxf(ml[h], e);
        }
    }
#pragma unroll
    for (int h = 0; h < HEADS; h++)
#pragma unroll
        for (int off = 16; off; off >>= 1)
            ml[h] = fmaxf(ml[h], __shfl_xor_sync(0xffffffffu, ml[h], off));

    __shared__ __align__(16) float wmax[NW][HEADS];
    __shared__ __align__(16) float mmax[HEADS];
    if (lane == 0) {
#pragma unroll
        for (int h = 0; h < HEADS; h++) wmax[warp][h] = ml[h];
    }
    __syncthreads();
    if (tid < HEADS) {
        float m = wmax[0][tid];
#pragma unroll
        for (int w = 1; w < NW; w++) m = fmaxf(m, wmax[w][tid]);
        mmax[tid] = m;
    }
    __syncthreads();
    float mAll[HEADS];
#pragma unroll
    for (int h = 0; h < HEADS; h++) mAll[h] = mmax[h];

    // pass 2: chunked exp + split weighted accumulate
    const int CHUNK = 128;
    __shared__ __align__(16) float sp[CHUNK][HEADS];
    __shared__ __align__(16) int sidx[CHUNK];
    float4 acc = make_float4(0.f, 0.f, 0.f, 0.f);
    float z = 0.f;

    for (int base = 0; base <= deg; base += CHUNK) {
        int len = min(CHUNK, deg + 1 - base);
        for (int i = tid; i < len; i += T) {
            int s = (base + i == deg) ? n : esrc[start + base + i];
            sidx[i] = s;
#pragma unroll
            for (int h = 0; h < HEADS; h++) {
                float e = ssrc[s * HEADS + h] + sd[h];
                e = e > 0.f ? e : 0.2f * e;
                sp[i][h] = __expf(e - mAll[h]);
            }
        }
        __syncthreads();
        for (int j = sub; j < len; j += 2) {
            float p = sp[j][head];
            z += p;
            int s = sidx[j];
            const uint2 raw = *(const uint2*)(hlin + (size_t)s * (HEADS * 128) + head * 128 + lane * 4);
            __half2 h0 = *(const __half2*)&raw.x;
            __half2 h1 = *(const __half2*)&raw.y;
            float2 f0 = __half22float2(h0);
            float2 f1 = __half22float2(h1);
            acc.x += p * f0.x;
            acc.y += p * f0.y;
            acc.z += p * f1.x;
            acc.w += p * f1.y;
        }
        __syncthreads();
    }

    // combine partial z across subs (z is warp-uniform)
    __shared__ __align__(16) float zsum[NW];
    if (lane == 0) zsum[warp] = z;
    __syncthreads();
    float invh = 1.f / (zsum[head] + zsum[head + HEADS] + 1e-16f);
    acc.x *= invh; acc.y *= invh; acc.z *= invh; acc.w *= invh;

    __shared__ __align__(16) float hb[NW * 128];
    *(float4*)&hb[warp * 128 + lane * 4] = acc;
    __syncthreads();
    if (tid < 32) {
        float v[4];
#pragma unroll
        for (int k = 0; k < 4; k++) {
            int c = tid * 4 + k;
            float s = 0.f;
#pragma unroll
            for (int w = 0; w < NW; w++) s += hb[w * 128 + c];
            float wv = s * (1.f / HEADS) + bias[c];
            if (ELUBN) {
                wv = wv > 0.f ? wv : (__expf(wv) - 1.f);                       // ELU
                wv = (wv - rm[c]) * rsqrtf(rv[c] + 1e-5f) * gam[c] + bet[c];   // BN eval
            }
            v[k] = wv;
        }
        if (HEADS == 1) {
            *(float4*)(outf + (size_t)n * 128 + tid * 4) = make_float4(v[0], v[1], v[2], v[3]);
        } else {
            __half2 o[2] = {__floats2half2_rn(v[0], v[1]), __floats2half2_rn(v[2], v[3])};
            *(uint2*)(outh + (size_t)n * 128 + tid * 4) = *(uint2*)o;
        }
    }
}

// ---------------- pooling ----------------
__global__ void pool_partial(const float* __restrict__ f, const int* __restrict__ batch,
                             float* __restrict__ tot, float* __restrict__ cnt)
{
    int n0 = blockIdx.x * 256;
    int c = threadIdx.x;
    if (n0 >= NN) return;
    int cur = batch[n0];
    float acc = 0.f;
    int lc = 0;
    for (int i = 0; i < 256; i++) {
        int n = n0 + i;
        if (n >= NN) break;
        int g = batch[n];
        if (g != cur) {
            atomicAdd(&tot[cur * 128 + c], acc);
            if (c == 0) atomicAdd(&cnt[cur], (float)lc);
            acc = 0.f; lc = 0; cur = g;
        }
        acc += f[(size_t)n * 128 + c];
        lc++;
    }
    if (lc) {
        atomicAdd(&tot[cur * 128 + c], acc);
        if (c == 0) atomicAdd(&cnt[cur], (float)lc);
    }
}

__global__ void pool_final(const float* __restrict__ tot, const float* __restrict__ cnt,
                           float* __restrict__ out)
{
    int g = blockIdx.x, c = threadIdx.x;
    out[g * 128 + c] = tot[g * 128 + c] / fmaxf(cnt[g], 1.f);
}

// ---------------- host orchestration ----------------
extern "C" void kernel_launch(void* const* d_in, const int* in_sizes, int n_in,
                              void* d_out, int out_size)
{
    const float* x    = (const float*)d_in[0];
    const int*   src  = (const int*)d_in[1];
    const int*   dst  = (const int*)d_in[2];
    const int*   batch= (const int*)d_in[3];
    const float* W1   = (const float*)d_in[4];
    const float* as1  = (const float*)d_in[5];
    const float* ad1  = (const float*)d_in[6];
    const float* b1   = (const float*)d_in[7];
    const float* gm1  = (const float*)d_in[8];
    const float* be1  = (const float*)d_in[9];
    const float* m1   = (const float*)d_in[10];
    const float* v1   = (const float*)d_in[11];
    const float* W2   = (const float*)d_in[12];
    const float* as2  = (const float*)d_in[13];
    const float* ad2  = (const float*)d_in[14];
    const float* b2   = (const float*)d_in[15];
    const float* gm2  = (const float*)d_in[16];
    const float* be2  = (const float*)d_in[17];
    const float* m2   = (const float*)d_in[18];
    const float* v2   = (const float*)d_in[19];
    const float* W3   = (const float*)d_in[20];
    const float* as3  = (const float*)d_in[21];
    const float* ad3  = (const float*)d_in[22];
    const float* b3   = (const float*)d_in[23];

    __half *hlinh, *xh, *w1h, *w2h, *w3h, *f1h, *f2h;
    float *f3, *ssrc, *sdst, *tot, *cnt;
    int *rowptr, *cursor, *deg, *esrc, *bsums;
    cudaGetSymbolAddress((void**)&hlinh, g_hlinh);
    cudaGetSymbolAddress((void**)&xh,    g_xh);
    cudaGetSymbolAddress((void**)&w1h,   g_w1h);
    cudaGetSymbolAddress((void**)&w2h,   g_w2h);
    cudaGetSymbolAddress((void**)&w3h,   g_w3h);
    cudaGetSymbolAddress((void**)&f1h,   g_f1h);
    cudaGetSymbolAddress((void**)&f2h,   g_f2h);
    cudaGetSymbolAddress((void**)&f3,    g_f3);
    cudaGetSymbolAddress((void**)&ssrc,  g_ssrc);
    cudaGetSymbolAddress((void**)&sdst,  g_sdst);
    cudaGetSymbolAddress((void**)&rowptr,g_rowptr);
    cudaGetSymbolAddress((void**)&cursor,g_cursor);
    cudaGetSymbolAddress((void**)&deg,   g_deg);
    cudaGetSymbolAddress((void**)&esrc,  g_esrc);
    cudaGetSymbolAddress((void**)&bsums, g_bsums);
    cudaGetSymbolAddress((void**)&tot,   g_tot);
    cudaGetSymbolAddress((void**)&cnt,   g_cnt);

    static cudaStream_t sB = nullptr, sC = nullptr;
    static cudaEvent_t evFork = nullptr, evB = nullptr, evC1 = nullptr, evC2 = nullptr;
    if (!sB) {
        cudaStreamCreateWithFlags(&sB, cudaStreamNonBlocking);
        cudaStreamCreateWithFlags(&sC, cudaStreamNonBlocking);
        cudaEventCreateWithFlags(&evFork, cudaEventDisableTiming);
        cudaEventCreateWithFlags(&evB, cudaEventDisableTiming);
        cudaEventCreateWithFlags(&evC1, cudaEventDisableTiming);
        cudaEventCreateWithFlags(&evC2, cudaEventDisableTiming);
    }

    const int MB = (NN + 127) / 128;  // 313

    // ---- fork ----
    cudaEventRecord(evFork, 0);
    cudaStreamWaitEvent(sB, evFork, 0);
    cudaStreamWaitEvent(sC, evFork, 0);

    // ---- stream B: CSR build ----
    kzero_i<<<(NN + 255) / 256, 256, 0, sB>>>(deg, NN);
    hist_k<<<(EE + 255) / 256, 256, 0, sB>>>(dst, deg);
    scan_block<<<(NN + 1023) / 1024, 1024, 0, sB>>>(deg, rowptr, bsums, NN);
    scan_sums<<<1, 32, 0, sB>>>(bsums, (NN + 1023) / 1024);
    scan_add<<<(NN + 255) / 256, 256, 0, sB>>>(rowptr, cursor, bsums, NN);
    scatter_k<<<(EE + 255) / 256, 256, 0, sB>>>(src, dst, cursor, esrc);
    cudaEventRecord(evB, sB);

    // ---- stream C: weight conversions + pool zeroing ----
    conv_half<<<(DIN * 512 / 8 + 255) / 256, 256, 0, sC>>>(W1, w1h, DIN * 512 / 8);
    cudaEventRecord(evC1, sC);
    conv_half<<<(128 * 512 / 8 + 255) / 256, 256, 0, sC>>>(W2, w2h, 128 * 512 / 8);
    conv_half<<<(128 * 128 / 8 + 255) / 256, 256, 0, sC>>>(W3, w3h, 128 * 128 / 8);
    kzero_pool<<<(GG * 128 + 255) / 256, 256, 0, sC>>>(tot, cnt);
    cudaEventRecord(evC2, sC);

    // ---- main stream ----
    conv_half<<<(NN * DIN / 8 + 255) / 256, 256>>>(x, xh, NN * DIN / 8);
    cudaStreamWaitEvent(0, evC1, 0);
    gemm_h<<<dim3(4, MB), 256>>>(NN, 256, 512, xh, w1h, hlinh, 4, as1, ad1, ssrc, sdst);
    cudaStreamWaitEvent(0, evB, 0);
    gat_agg<4, true><<<NN, 256>>>(hlinh, ssrc, sdst, rowptr, esrc, b1, gm1, be1, m1, v1, f1h, nullptr);

    cudaStreamWaitEvent(0, evC2, 0);
    gemm_h<<<dim3(4, MB), 256>>>(NN, 128, 512, f1h, w2h, hlinh, 4, as2, ad2, ssrc, sdst);
    gat_agg<4, true><<<NN, 256>>>(hlinh, ssrc, sdst, rowptr, esrc, b2, gm2, be2, m2, v2, f2h, nullptr);

    gemm_h<<<dim3(1, MB), 256>>>(NN, 128, 128, f2h, w3h, hlinh, 1, as3, ad3, ssrc, sdst);
    gat_agg<1, false><<<NN, 64>>>(hlinh, ssrc, sdst, rowptr, esrc, b3,
                                  nullptr, nullptr, nullptr, nullptr, nullptr, f3);

    // ---- global mean pool ----
    pool_partial<<<(NN + 255) / 256, 128>>>(f3, batch, tot, cnt);
    pool_final<<<GG, 128>>>(tot, cnt, (float*)d_out);
}

// round 13
// speedup vs baseline: 1.2312x; 1.2312x over previous
#include <cuda_runtime.h>
#include <cuda_fp16.h>
#include <mma.h>
#include <cstdint>

using namespace nvcuda;

// Problem constants (fixed by the dataset)
#define NN 40000
#define EE 400000
#define GG 256
#define DIN 256
#define HH 4

#define MPAD 40064   // 313 * 128, padded rows for unguarded stores

// ---------------- scratch (static device globals; no allocation) ----------------
__device__ __half g_hlinh[(size_t)MPAD * 512];  // GEMM output (half), current layer
__device__ __half g_xh[(size_t)NN * DIN];       // x converted to half
__device__ __half g_w1h[DIN * 512];
__device__ __half g_w2h[128 * 512];
__device__ __half g_w3h[128 * 128];
__device__ __half g_f1h[(size_t)NN * 128];      // layer1 out (half)
__device__ __half g_f2h[(size_t)NN * 128];      // layer2 out (half)
__device__ float  g_f3[(size_t)NN * 128];       // layer3 out (float, feeds pool)
__device__ float  g_ssrc[NN * HH];
__device__ float  g_sdst[NN * HH];
__device__ int    g_rowptr[NN + 1];
__device__ int    g_cursor[NN];
__device__ int    g_deg[NN];
__device__ int    g_esrc[EE];
__device__ int    g_bsums[64];
__device__ float  g_tot[GG * 128];
__device__ float  g_cnt[GG];

// ---------------- utility kernels ----------------
__global__ void kzero_i(int* p, int n) {
    int i = blockIdx.x * blockDim.x + threadIdx.x;
    if (i < n) p[i] = 0;
}
__global__ void kzero_pool(float* tot, float* cnt) {
    int i = blockIdx.x * blockDim.x + threadIdx.x;
    if (i < GG * 128) tot[i] = 0.f;
    if (i < GG) cnt[i] = 0.f;
}

// convert fp32 array to half, 8 elements per thread (n % 8 == 0)
__global__ void conv_half(const float* __restrict__ in, __half* __restrict__ out, int n8) {
    int i = blockIdx.x * blockDim.x + threadIdx.x;
    if (i < n8) {
        float4 a = ((const float4*)in)[2 * i];
        float4 b = ((const float4*)in)[2 * i + 1];
        __half2 h[4];
        h[0] = __floats2half2_rn(a.x, a.y);
        h[1] = __floats2half2_rn(a.z, a.w);
        h[2] = __floats2half2_rn(b.x, b.y);
        h[3] = __floats2half2_rn(b.z, b.w);
        ((uint4*)out)[i] = *(uint4*)h;
    }
}

__global__ void hist_k(const int* __restrict__ dst, int* __restrict__ deg) {
    int e = blockIdx.x * blockDim.x + threadIdx.x;
    if (e < EE) atomicAdd(&deg[dst[e]], 1);
}

__global__ void scan_block(const int* __restrict__ deg, int* __restrict__ rowptr,
                           int* __restrict__ bsums, int n) {
    __shared__ int tmp[1024];
    int i = blockIdx.x * 1024 + threadIdx.x;
    int v = (i < n) ? deg[i] : 0;
    tmp[threadIdx.x] = v;
    __syncthreads();
    for (int off = 1; off < 1024; off <<= 1) {
        int t = (threadIdx.x >= off) ? tmp[threadIdx.x - off] : 0;
        __syncthreads();
        tmp[threadIdx.x] += t;
        __syncthreads();
    }
    if (i < n) rowptr[i] = tmp[threadIdx.x] - v;  // exclusive
    if (threadIdx.x == 1023) bsums[blockIdx.x] = tmp[1023];
}

__global__ void scan_sums(int* bsums, int nb) {
    if (threadIdx.x == 0 && blockIdx.x == 0) {
        int run = 0;
        for (int b = 0; b < nb; b++) { int v = bsums[b]; bsums[b] = run; run += v; }
    }
}

__global__ void scan_add(int* __restrict__ rowptr, int* __restrict__ cursor,
                         const int* __restrict__ bsums, int n) {
    int i = blockIdx.x * blockDim.x + threadIdx.x;
    if (i < n) {
        int v = rowptr[i] + bsums[i >> 10];
        rowptr[i] = v;
        cursor[i] = v;
    }
    if (i == 0) rowptr[n] = EE;
}

__global__ void scatter_k(const int* __restrict__ src, const int* __restrict__ dst,
                          int* __restrict__ cursor, int* __restrict__ esrc) {
    int e = blockIdx.x * blockDim.x + threadIdx.x;
    if (e < EE) {
        int pos = atomicAdd(&cursor[dst[e]], 1);
        esrc[pos] = src[e];
    }
}

// ---------------- FP16 tensor-core GEMM + fused attention-score epilogue ----------
#define GBM 128
#define GBN 128
#define GBK 32
#define ALD 40     // A smem row stride (halfs)
#define BLD 136    // B smem row stride (halfs)
#define AB_BYTES (2 * GBM * ALD * 2 + 2 * GBK * BLD * 2)   // 37888
#define CS_LD 68   // epilogue float staging stride

__global__ __launch_bounds__(256) void gemm_h(int M, int K, int Nc,
    const __half* __restrict__ A, const __half* __restrict__ B, __half* __restrict__ C,
    int heads, const float* __restrict__ asrc, const float* __restrict__ adst,
    float* __restrict__ ssrc, float* __restrict__ sdst)
{
    __shared__ __align__(16) char smem_raw[AB_BYTES];   // reused by epilogue
    __half* Ah = (__half*)smem_raw;                     // [2][GBM*ALD]
    __half* Bh = Ah + 2 * GBM * ALD;                    // [2][GBK*BLD]

    const int tid = threadIdx.x;
    const int warpId = tid >> 5;
    const int warpM = warpId & 3;
    const int warpN = warpId >> 2;
    const int head = blockIdx.x;
    const int blockM = blockIdx.y * GBM;
    const int blockN = head * GBN;

    const unsigned int sA = (unsigned int)__cvta_generic_to_shared(Ah);
    const unsigned int sB = (unsigned int)__cvta_generic_to_shared(Bh);

    wmma::fragment<wmma::accumulator, 16, 16, 16, float> acc[2][4];
#pragma unroll
    for (int i = 0; i < 2; i++)
#pragma unroll
        for (int j = 0; j < 4; j++) wmma::fill_fragment(acc[i][j], 0.f);

    const int nsteps = K / GBK;

    auto stage = [&](int buf, int k0) {
#pragma unroll
        for (int q = 0; q < 2; q++) {
            int c = tid + q * 256;
            int ar = c >> 2, ac = (c & 3) * 8;
            int gr = blockM + ar;
            const __half* gpA = A + (size_t)gr * K + k0 + ac;
            unsigned int saA = sA + (unsigned int)(buf * GBM * ALD + ar * ALD + ac) * 2u;
            int sz = (gr < M) ? 16 : 0;
            asm volatile("cp.async.cg.shared.global [%0], [%1], 16, %2;\n"
                         :: "r"(saA), "l"(gpA), "r"(sz));
            int br = c >> 4, bc = (c & 15) * 8;
            const __half* gpB = B + (size_t)(k0 + br) * Nc + blockN + bc;
            unsigned int saB = sB + (unsigned int)(buf * GBK * BLD + br * BLD + bc) * 2u;
            asm volatile("cp.async.cg.shared.global [%0], [%1], 16;\n"
                         :: "r"(saB), "l"(gpB));
        }
        asm volatile("cp.async.commit_group;\n");
    };

    stage(0, 0);

    for (int s = 0; s < nsteps; s++) {
        const int p = s & 1;
        if (s + 1 < nsteps) {
            stage(1 - p, (s + 1) * GBK);
            asm volatile("cp.async.wait_group 1;\n");
        } else {
            asm volatile("cp.async.wait_group 0;\n");
        }
        __syncthreads();

        const __half* ap = Ah + p * GBM * ALD;
        const __half* bp = Bh + p * GBK * BLD;
#pragma unroll
        for (int kk = 0; kk < GBK; kk += 16) {
            wmma::fragment<wmma::matrix_a, 16, 16, 16, __half, wmma::row_major> af[2];
            wmma::fragment<wmma::matrix_b, 16, 16, 16, __half, wmma::row_major> bf[4];
#pragma unroll
            for (int i = 0; i < 2; i++)
                wmma::load_matrix_sync(af[i], ap + (warpM * 32 + i * 16) * ALD + kk, ALD);
#pragma unroll
            for (int j = 0; j < 4; j++)
                wmma::load_matrix_sync(bf[j], bp + kk * BLD + warpN * 64 + j * 16, BLD);
#pragma unroll
            for (int i = 0; i < 2; i++)
#pragma unroll
                for (int j = 0; j < 4; j++)
                    wmma::mma_sync(acc[i][j], af[i], bf[j], acc[i][j]);
        }
        __syncthreads();
    }

    // fused epilogue: acc -> smem(fp32) -> half C + attention dots
    float* Cs = (float*)smem_raw;            // [128][CS_LD]
    const float* asrc_h = asrc + head * 128;
    const float* adst_h = adst + head * 128;
    const int row = tid >> 1;
    const int cseg = (tid & 1) * 32;
    float ds = 0.f, dd = 0.f;

#pragma unroll
    for (int p = 0; p < 2; p++) {
        if (warpN == p) {
#pragma unroll
            for (int i = 0; i < 2; i++)
#pragma unroll
                for (int j = 0; j < 4; j++)
                    wmma::store_matrix_sync(Cs + (warpM * 32 + i * 16) * CS_LD + j * 16,
                                            acc[i][j], CS_LD, wmma::mem_row_major);
        }
        __syncthreads();

        const float* crow = Cs + row * CS_LD + cseg;
        __half2 hbuf[16];
        int colbase = p * 64 + cseg;
#pragma unroll
        for (int k = 0; k < 32; k += 2) {
            float a0 = crow[k], a1 = crow[k + 1];
            hbuf[k >> 1] = __floats2half2_rn(a0, a1);
            ds += a0 * asrc_h[colbase + k] + a1 * asrc_h[colbase + k + 1];
            dd += a0 * adst_h[colbase + k] + a1 * adst_h[colbase + k + 1];
        }
        uint4* dstp = (uint4*)(C + (size_t)(blockM + row) * Nc + blockN + colbase);
        const uint4* srcv = (const uint4*)hbuf;
        dstp[0] = srcv[0]; dstp[1] = srcv[1]; dstp[2] = srcv[2]; dstp[3] = srcv[3];
        __syncthreads();
    }

    ds += __shfl_xor_sync(0xffffffffu, ds, 1);
    dd += __shfl_xor_sync(0xffffffffu, dd, 1);
    int gr = blockM + row;
    if ((tid & 1) == 0 && gr < M) {
        ssrc[gr * heads + head] = ds;
        sdst[gr * heads + head] = dd;
    }
}

// ---------------- per-dst aggregation (R10 shape: HEADS*32 threads) ------------
// j-loop software-prefetches the gather for edge j+1 while accumulating edge j.
template <int HEADS, bool ELUBN>
__global__ void gat_agg(const __half* __restrict__ hlin,
                        const float* __restrict__ ssrc, const float* __restrict__ sdst,
                        const int* __restrict__ rowptr, const int* __restrict__ esrc,
                        const float* __restrict__ bias,
                        const float* __restrict__ gam, const float* __restrict__ bet,
                        const float* __restrict__ rm, const float* __restrict__ rv,
                        __half* __restrict__ outh, float* __restrict__ outf)
{
    const int T = HEADS * 32;
    const int n = blockIdx.x;
    const int tid = threadIdx.x;
    const int head = tid >> 5;
    const int lane = tid & 31;
    const int start = rowptr[n];
    const int deg = rowptr[n + 1] - start;   // real in-edges; +1 implicit self loop

    float sd[HEADS];
#pragma unroll
    for (int h = 0; h < HEADS; h++) sd[h] = sdst[n * HEADS + h];

    // pass 1: per-head max over edges (incl. self loop at index deg)
    float ml[HEADS];
#pragma unroll
    for (int h = 0; h < HEADS; h++) ml[h] = -1e30f;
    for (int i = tid; i <= deg; i += T) {
        int s = (i == deg) ? n : esrc[start + i];
#pragma unroll
        for (int h = 0; h < HEADS; h++) {
            float e = ssrc[s * HEADS + h] + sd[h];
            e = e > 0.f ? e : 0.2f * e;
            ml[h] = fmaxf(ml[h], e);
        }
    }
#pragma unroll
    for (int h = 0; h < HEADS; h++)
#pragma unroll
        for (int off = 16; off; off >>= 1)
            ml[h] = fmaxf(ml[h], __shfl_xor_sync(0xffffffffu, ml[h], off));

    __shared__ __align__(16) float wmax[HEADS][HEADS];
    __shared__ __align__(16) float mmax[HEADS];
    float mAll[HEADS];
    if (HEADS > 1) {
        if (lane == 0) {
#pragma unroll
            for (int h = 0; h < HEADS; h++) wmax[head][h] = ml[h];
        }
        __syncthreads();
        if (tid < HEADS) {
            float m = wmax[0][tid];
#pragma unroll
            for (int w = 1; w < HEADS; w++) m = fmaxf(m, wmax[w][tid]);
            mmax[tid] = m;
        }
        __syncthreads();
#pragma unroll
        for (int h = 0; h < HEADS; h++) mAll[h] = mmax[h];
    } else {
        mAll[0] = ml[0];
    }

    // pass 2: chunked exp + weighted accumulate (half gathers, prefetched)
    const int CHUNK = 128;
    __shared__ __align__(16) float sp[CHUNK][HEADS];
    __shared__ __align__(16) int sidx[CHUNK];
    float4 acc = make_float4(0.f, 0.f, 0.f, 0.f);
    float z = 0.f;

    const size_t rowstride = HEADS * 128;
    const int coloff = head * 128 + lane * 4;

    for (int base = 0; base <= deg; base += CHUNK) {
        int len = min(CHUNK, deg + 1 - base);
        for (int i = tid; i < len; i += T) {
            int s = (base + i == deg) ? n : esrc[start + base + i];
            sidx[i] = s;
#pragma unroll
            for (int h = 0; h < HEADS; h++) {
                float e = ssrc[s * HEADS + h] + sd[h];
                e = e > 0.f ? e : 0.2f * e;
                sp[i][h] = __expf(e - mAll[h]);
            }
        }
        __syncthreads();

        uint2 raw = *(const uint2*)(hlin + (size_t)sidx[0] * rowstride + coloff);
        for (int j = 0; j < len; j++) {
            uint2 cur = raw;
            if (j + 1 < len)
                raw = *(const uint2*)(hlin + (size_t)sidx[j + 1] * rowstride + coloff);
            float p = sp[j][head];
            z += p;
            __half2 h0 = *(const __half2*)&cur.x;
            __half2 h1 = *(const __half2*)&cur.y;
            float2 f0 = __half22float2(h0);
            float2 f1 = __half22float2(h1);
            acc.x += p * f0.x;
            acc.y += p * f0.y;
            acc.z += p * f1.x;
            acc.w += p * f1.y;
        }
        __syncthreads();
    }

    float inv = 1.f / (z + 1e-16f);
    acc.x *= inv; acc.y *= inv; acc.z *= inv; acc.w *= inv;

    if (HEADS == 1) {
        float v[4] = {acc.x, acc.y, acc.z, acc.w};
#pragma unroll
        for (int k = 0; k < 4; k++) {
            int c = lane * 4 + k;
            outf[(size_t)n * 128 + c] = v[k] + bias[c];
        }
    } else {
        __shared__ __align__(16) float hb[HEADS * 128];
        *(float4*)&hb[head * 128 + lane * 4] = acc;
        __syncthreads();
        if (tid < 32) {
            float v[4];
#pragma unroll
            for (int k = 0; k < 4; k++) {
                int c = tid * 4 + k;
                float s = 0.f;
#pragma unroll
                for (int h = 0; h < HEADS; h++) s += hb[h * 128 + c];
                float w = s * (1.f / HEADS) + bias[c];
                if (ELUBN) {
                    w = w > 0.f ? w : (__expf(w) - 1.f);                       // ELU
                    w = (w - rm[c]) * rsqrtf(rv[c] + 1e-5f) * gam[c] + bet[c]; // BN eval
                }
                v[k] = w;
            }
            __half2 o[2] = {__floats2half2_rn(v[0], v[1]), __floats2half2_rn(v[2], v[3])};
            *(uint2*)(outh + (size_t)n * 128 + tid * 4) = *(uint2*)o;
        }
    }
}

// ---------------- pooling ----------------
__global__ void pool_partial(const float* __restrict__ f, const int* __restrict__ batch,
                             float* __restrict__ tot, float* __restrict__ cnt)
{
    int n0 = blockIdx.x * 256;
    int c = threadIdx.x;
    if (n0 >= NN) return;
    int cur = batch[n0];
    float acc = 0.f;
    int lc = 0;
    for (int i = 0; i < 256; i++) {
        int n = n0 + i;
        if (n >= NN) break;
        int g = batch[n];
        if (g != cur) {
            atomicAdd(&tot[cur * 128 + c], acc);
            if (c == 0) atomicAdd(&cnt[cur], (float)lc);
            acc = 0.f; lc = 0; cur = g;
        }
        acc += f[(size_t)n * 128 + c];
        lc++;
    }
    if (lc) {
        atomicAdd(&tot[cur * 128 + c], acc);
        if (c == 0) atomicAdd(&cnt[cur], (float)lc);
    }
}

__global__ void pool_final(const float* __restrict__ tot, const float* __restrict__ cnt,
                           float* __restrict__ out)
{
    int g = blockIdx.x, c = threadIdx.x;
    out[g * 128 + c] = tot[g * 128 + c] / fmaxf(cnt[g], 1.f);
}

// ---------------- host orchestration ----------------
extern "C" void kernel_launch(void* const* d_in, const int* in_sizes, int n_in,
                              void* d_out, int out_size)
{
    const float* x    = (const float*)d_in[0];
    const int*   src  = (const int*)d_in[1];
    const int*   dst  = (const int*)d_in[2];
    const int*   batch= (const int*)d_in[3];
    const float* W1   = (const float*)d_in[4];
    const float* as1  = (const float*)d_in[5];
    const float* ad1  = (const float*)d_in[6];
    const float* b1   = (const float*)d_in[7];
    const float* gm1  = (const float*)d_in[8];
    const float* be1  = (const float*)d_in[9];
    const float* m1   = (const float*)d_in[10];
    const float* v1   = (const float*)d_in[11];
    const float* W2   = (const float*)d_in[12];
    const float* as2  = (const float*)d_in[13];
    const float* ad2  = (const float*)d_in[14];
    const float* b2   = (const float*)d_in[15];
    const float* gm2  = (const float*)d_in[16];
    const float* be2  = (const float*)d_in[17];
    const float* m2   = (const float*)d_in[18];
    const float* v2   = (const float*)d_in[19];
    const float* W3   = (const float*)d_in[20];
    const float* as3  = (const float*)d_in[21];
    const float* ad3  = (const float*)d_in[22];
    const float* b3   = (const float*)d_in[23];

    __half *hlinh, *xh, *w1h, *w2h, *w3h, *f1h, *f2h;
    float *f3, *ssrc, *sdst, *tot, *cnt;
    int *rowptr, *cursor, *deg, *esrc, *bsums;
    cudaGetSymbolAddress((void**)&hlinh, g_hlinh);
    cudaGetSymbolAddress((void**)&xh,    g_xh);
    cudaGetSymbolAddress((void**)&w1h,   g_w1h);
    cudaGetSymbolAddress((void**)&w2h,   g_w2h);
    cudaGetSymbolAddress((void**)&w3h,   g_w3h);
    cudaGetSymbolAddress((void**)&f1h,   g_f1h);
    cudaGetSymbolAddress((void**)&f2h,   g_f2h);
    cudaGetSymbolAddress((void**)&f3,    g_f3);
    cudaGetSymbolAddress((void**)&ssrc,  g_ssrc);
    cudaGetSymbolAddress((void**)&sdst,  g_sdst);
    cudaGetSymbolAddress((void**)&rowptr,g_rowptr);
    cudaGetSymbolAddress((void**)&cursor,g_cursor);
    cudaGetSymbolAddress((void**)&deg,   g_deg);
    cudaGetSymbolAddress((void**)&esrc,  g_esrc);
    cudaGetSymbolAddress((void**)&bsums, g_bsums);
    cudaGetSymbolAddress((void**)&tot,   g_tot);
    cudaGetSymbolAddress((void**)&cnt,   g_cnt);

    static cudaStream_t sB = nullptr, sC = nullptr;
    static cudaEvent_t evFork = nullptr, evB = nullptr, evC1 = nullptr, evC2 = nullptr;
    if (!sB) {
        cudaStreamCreateWithFlags(&sB, cudaStreamNonBlocking);
        cudaStreamCreateWithFlags(&sC, cudaStreamNonBlocking);
        cudaEventCreateWithFlags(&evFork, cudaEventDisableTiming);
        cudaEventCreateWithFlags(&evB, cudaEventDisableTiming);
        cudaEventCreateWithFlags(&evC1, cudaEventDisableTiming);
        cudaEventCreateWithFlags(&evC2, cudaEventDisableTiming);
    }

    const int MB = (NN + 127) / 128;  // 313

    // ---- fork ----
    cudaEventRecord(evFork, 0);
    cudaStreamWaitEvent(sB, evFork, 0);
    cudaStreamWaitEvent(sC, evFork, 0);

    // ---- stream B: CSR build ----
    kzero_i<<<(NN + 255) / 256, 256, 0, sB>>>(deg, NN);
    hist_k<<<(EE + 255) / 256, 256, 0, sB>>>(dst, deg);
    scan_block<<<(NN + 1023) / 1024, 1024, 0, sB>>>(deg, rowptr, bsums, NN);
    scan_sums<<<1, 32, 0, sB>>>(bsums, (NN + 1023) / 1024);
    scan_add<<<(NN + 255) / 256, 256, 0, sB>>>(rowptr, cursor, bsums, NN);
    scatter_k<<<(EE + 255) / 256, 256, 0, sB>>>(src, dst, cursor, esrc);
    cudaEventRecord(evB, sB);

    // ---- stream C: weight conversions + pool zeroing ----
    conv_half<<<(DIN * 512 / 8 + 255) / 256, 256, 0, sC>>>(W1, w1h, DIN * 512 / 8);
    cudaEventRecord(evC1, sC);
    conv_half<<<(128 * 512 / 8 + 255) / 256, 256, 0, sC>>>(W2, w2h, 128 * 512 / 8);
    conv_half<<<(128 * 128 / 8 + 255) / 256, 256, 0, sC>>>(W3, w3h, 128 * 128 / 8);
    kzero_pool<<<(GG * 128 + 255) / 256, 256, 0, sC>>>(tot, cnt);
    cudaEventRecord(evC2, sC);

    // ---- main stream ----
    conv_half<<<(NN * DIN / 8 + 255) / 256, 256>>>(x, xh, NN * DIN / 8);
    cudaStreamWaitEvent(0, evC1, 0);
    gemm_h<<<dim3(4, MB), 256>>>(NN, 256, 512, xh, w1h, hlinh, 4, as1, ad1, ssrc, sdst);
    cudaStreamWaitEvent(0, evB, 0);
    gat_agg<4, true><<<NN, 128>>>(hlinh, ssrc, sdst, rowptr, esrc, b1, gm1, be1, m1, v1, f1h, nullptr);

    cudaStreamWaitEvent(0, evC2, 0);
    gemm_h<<<dim3(4, MB), 256>>>(NN, 128, 512, f1h, w2h, hlinh, 4, as2, ad2, ssrc, sdst);
    gat_agg<4, true><<<NN, 128>>>(hlinh, ssrc, sdst, rowptr, esrc, b2, gm2, be2, m2, v2, f2h, nullptr);

    gemm_h<<<dim3(1, MB), 256>>>(NN, 128, 128, f2h, w3h, hlinh, 1, as3, ad3, ssrc, sdst);
    gat_agg<1, false><<<NN, 32>>>(hlinh, ssrc, sdst, rowptr, esrc, b3,
                                  nullptr, nullptr, nullptr, nullptr, nullptr, f3);

    // ---- global mean pool ----
    pool_partial<<<(NN + 255) / 256, 128>>>(f3, batch, tot, cnt);
    pool_final<<<GG, 128>>>(tot, cnt, (float*)d_out);
}

// round 14
// speedup vs baseline: 1.3814x; 1.1220x over previous
#include <cuda_runtime.h>
#include <cuda_fp16.h>
#include <mma.h>
#include <cstdint>

using namespace nvcuda;

// Problem constants (fixed by the dataset)
#define NN 40000
#define EE 400000
#define GG 256
#define DIN 256
#define HH 4

#define MPAD 40064   // 313 * 128, padded rows for unguarded stores

// ---------------- scratch (static device globals; no allocation) ----------------
__device__ __half g_hlinh[(size_t)MPAD * 512];  // GEMM output (half), current layer
__device__ __half g_xh[(size_t)NN * DIN];       // x converted to half
__device__ __half g_w1h[DIN * 512];
__device__ __half g_w2h[128 * 512];
__device__ __half g_w3h[128 * 128];
__device__ __half g_f1h[(size_t)NN * 128];      // layer1 out (half)
__device__ __half g_f2h[(size_t)NN * 128];      // layer2 out (half)
__device__ float  g_f3[(size_t)NN * 128];       // layer3 out (float, feeds pool)
__device__ float  g_ssrc[NN * HH];
__device__ float  g_sdst[NN * HH];
__device__ int    g_rowptr[NN + 1];
__device__ int    g_cursor[NN];
__device__ int    g_deg[NN];
__device__ int    g_esrc[EE];
__device__ int    g_bsums[64];
__device__ float  g_tot[GG * 128];
__device__ float  g_cnt[GG];

// ---------------- utility kernels ----------------
__global__ void kzero_i(int* p, int n) {
    int i = blockIdx.x * blockDim.x + threadIdx.x;
    if (i < n) p[i] = 0;
}
__global__ void kzero_pool(float* tot, float* cnt) {
    int i = blockIdx.x * blockDim.x + threadIdx.x;
    if (i < GG * 128) tot[i] = 0.f;
    if (i < GG) cnt[i] = 0.f;
}

// convert fp32 array to half, 8 elements per thread (n % 8 == 0)
__global__ void conv_half(const float* __restrict__ in, __half* __restrict__ out, int n8) {
    int i = blockIdx.x * blockDim.x + threadIdx.x;
    if (i < n8) {
        float4 a = ((const float4*)in)[2 * i];
        float4 b = ((const float4*)in)[2 * i + 1];
        __half2 h[4];
        h[0] = __floats2half2_rn(a.x, a.y);
        h[1] = __floats2half2_rn(a.z, a.w);
        h[2] = __floats2half2_rn(b.x, b.y);
        h[3] = __floats2half2_rn(b.z, b.w);
        ((uint4*)out)[i] = *(uint4*)h;
    }
}

__global__ void hist_k(const int* __restrict__ dst, int* __restrict__ deg) {
    int e = blockIdx.x * blockDim.x + threadIdx.x;
    if (e < EE) atomicAdd(&deg[dst[e]], 1);
}

__global__ void scan_block(const int* __restrict__ deg, int* __restrict__ rowptr,
                           int* __restrict__ bsums, int n) {
    __shared__ int tmp[1024];
    int i = blockIdx.x * 1024 + threadIdx.x;
    int v = (i < n) ? deg[i] : 0;
    tmp[threadIdx.x] = v;
    __syncthreads();
    for (int off = 1; off < 1024; off <<= 1) {
        int t = (threadIdx.x >= off) ? tmp[threadIdx.x - off] : 0;
        __syncthreads();
        tmp[threadIdx.x] += t;
        __syncthreads();
    }
    if (i < n) rowptr[i] = tmp[threadIdx.x] - v;  // exclusive
    if (threadIdx.x == 1023) bsums[blockIdx.x] = tmp[1023];
}

__global__ void scan_sums(int* bsums, int nb) {
    if (threadIdx.x == 0 && blockIdx.x == 0) {
        int run = 0;
        for (int b = 0; b < nb; b++) { int v = bsums[b]; bsums[b] = run; run += v; }
    }
}

__global__ void scan_add(int* __restrict__ rowptr, int* __restrict__ cursor,
                         const int* __restrict__ bsums, int n) {
    int i = blockIdx.x * blockDim.x + threadIdx.x;
    if (i < n) {
        int v = rowptr[i] + bsums[i >> 10];
        rowptr[i] = v;
        cursor[i] = v;
    }
    if (i == 0) rowptr[n] = EE;
}

__global__ void scatter_k(const int* __restrict__ src, const int* __restrict__ dst,
                          int* __restrict__ cursor, int* __restrict__ esrc) {
    int e = blockIdx.x * blockDim.x + threadIdx.x;
    if (e < EE) {
        int pos = atomicAdd(&cursor[dst[e]], 1);
        esrc[pos] = src[e];
    }
}

// ---------------- FP16 tensor-core GEMM + fused attention-score epilogue ----------
#define GBM 128
#define GBN 128
#define GBK 32
#define ALD 40     // A smem row stride (halfs)
#define BLD 136    // B smem row stride (halfs)
#define AB_BYTES (2 * GBM * ALD * 2 + 2 * GBK * BLD * 2)   // 37888
#define CS_LD 68   // epilogue float staging stride

__global__ __launch_bounds__(256) void gemm_h(int M, int K, int Nc,
    const __half* __restrict__ A, const __half* __restrict__ B, __half* __restrict__ C,
    int heads, const float* __restrict__ asrc, const float* __restrict__ adst,
    float* __restrict__ ssrc, float* __restrict__ sdst)
{
    __shared__ __align__(16) char smem_raw[AB_BYTES];   // reused by epilogue
    __half* Ah = (__half*)smem_raw;                     // [2][GBM*ALD]
    __half* Bh = Ah + 2 * GBM * ALD;                    // [2][GBK*BLD]

    const int tid = threadIdx.x;
    const int warpId = tid >> 5;
    const int warpM = warpId & 3;
    const int warpN = warpId >> 2;
    const int head = blockIdx.x;
    const int blockM = blockIdx.y * GBM;
    const int blockN = head * GBN;

    const unsigned int sA = (unsigned int)__cvta_generic_to_shared(Ah);
    const unsigned int sB = (unsigned int)__cvta_generic_to_shared(Bh);

    wmma::fragment<wmma::accumulator, 16, 16, 16, float> acc[2][4];
#pragma unroll
    for (int i = 0; i < 2; i++)
#pragma unroll
        for (int j = 0; j < 4; j++) wmma::fill_fragment(acc[i][j], 0.f);

    const int nsteps = K / GBK;

    auto stage = [&](int buf, int k0) {
#pragma unroll
        for (int q = 0; q < 2; q++) {
            int c = tid + q * 256;
            int ar = c >> 2, ac = (c & 3) * 8;
            int gr = blockM + ar;
            const __half* gpA = A + (size_t)gr * K + k0 + ac;
            unsigned int saA = sA + (unsigned int)(buf * GBM * ALD + ar * ALD + ac) * 2u;
            int sz = (gr < M) ? 16 : 0;
            asm volatile("cp.async.cg.shared.global [%0], [%1], 16, %2;\n"
                         :: "r"(saA), "l"(gpA), "r"(sz));
            int br = c >> 4, bc = (c & 15) * 8;
            const __half* gpB = B + (size_t)(k0 + br) * Nc + blockN + bc;
            unsigned int saB = sB + (unsigned int)(buf * GBK * BLD + br * BLD + bc) * 2u;
            asm volatile("cp.async.cg.shared.global [%0], [%1], 16;\n"
                         :: "r"(saB), "l"(gpB));
        }
        asm volatile("cp.async.commit_group;\n");
    };

    stage(0, 0);

    for (int s = 0; s < nsteps; s++) {
        const int p = s & 1;
        if (s + 1 < nsteps) {
            stage(1 - p, (s + 1) * GBK);
            asm volatile("cp.async.wait_group 1;\n");
        } else {
            asm volatile("cp.async.wait_group 0;\n");
        }
        __syncthreads();

        const __half* ap = Ah + p * GBM * ALD;
        const __half* bp = Bh + p * GBK * BLD;
#pragma unroll
        for (int kk = 0; kk < GBK; kk += 16) {
            wmma::fragment<wmma::matrix_a, 16, 16, 16, __half, wmma::row_major> af[2];
            wmma::fragment<wmma::matrix_b, 16, 16, 16, __half, wmma::row_major> bf[4];
#pragma unroll
            for (int i = 0; i < 2; i++)
                wmma::load_matrix_sync(af[i], ap + (warpM * 32 + i * 16) * ALD + kk, ALD);
#pragma unroll
            for (int j = 0; j < 4; j++)
                wmma::load_matrix_sync(bf[j], bp + kk * BLD + warpN * 64 + j * 16, BLD);
#pragma unroll
            for (int i = 0; i < 2; i++)
#pragma unroll
                for (int j = 0; j < 4; j++)
                    wmma::mma_sync(acc[i][j], af[i], bf[j], acc[i][j]);
        }
        __syncthreads();
    }

    // fused epilogue: acc -> smem(fp32) -> half C + attention dots
    float* Cs = (float*)smem_raw;            // [128][CS_LD]
    const float* asrc_h = asrc + head * 128;
    const float* adst_h = adst + head * 128;
    const int row = tid >> 1;
    const int cseg = (tid & 1) * 32;
    float ds = 0.f, dd = 0.f;

#pragma unroll
    for (int p = 0; p < 2; p++) {
        if (warpN == p) {
#pragma unroll
            for (int i = 0; i < 2; i++)
#pragma unroll
                for (int j = 0; j < 4; j++)
                    wmma::store_matrix_sync(Cs + (warpM * 32 + i * 16) * CS_LD + j * 16,
                                            acc[i][j], CS_LD, wmma::mem_row_major);
        }
        __syncthreads();

        const float* crow = Cs + row * CS_LD + cseg;
        __half2 hbuf[16];
        int colbase = p * 64 + cseg;
#pragma unroll
        for (int k = 0; k < 32; k += 2) {
            float a0 = crow[k], a1 = crow[k + 1];
            hbuf[k >> 1] = __floats2half2_rn(a0, a1);
            ds += a0 * asrc_h[colbase + k] + a1 * asrc_h[colbase + k + 1];
            dd += a0 * adst_h[colbase + k] + a1 * adst_h[colbase + k + 1];
        }
        uint4* dstp = (uint4*)(C + (size_t)(blockM + row) * Nc + blockN + colbase);
        const uint4* srcv = (const uint4*)hbuf;
        dstp[0] = srcv[0]; dstp[1] = srcv[1]; dstp[2] = srcv[2]; dstp[3] = srcv[3];
        __syncthreads();
    }

    ds += __shfl_xor_sync(0xffffffffu, ds, 1);
    dd += __shfl_xor_sync(0xffffffffu, dd, 1);
    int gr = blockM + row;
    if ((tid & 1) == 0 && gr < M) {
        ssrc[gr * heads + head] = ds;
        sdst[gr * heads + head] = dd;
    }
}

// ---------------- per-dst aggregation (HEADS*32 threads, R10 j-loop) ------------
// Fast path (deg < CHUNK): single global pass computes logits into smem, max is
// reduced from smem-resident values, exp applied in smem — pass-1 global re-reads
// eliminated. Slow path: exact two-pass (R10).
template <int HEADS, bool ELUBN>
__global__ void gat_agg(const __half* __restrict__ hlin,
                        const float* __restrict__ ssrc, const float* __restrict__ sdst,
                        const int* __restrict__ rowptr, const int* __restrict__ esrc,
                        const float* __restrict__ bias,
                        const float* __restrict__ gam, const float* __restrict__ bet,
                        const float* __restrict__ rm, const float* __restrict__ rv,
                        __half* __restrict__ outh, float* __restrict__ outf)
{
    const int T = HEADS * 32;
    const int n = blockIdx.x;
    const int tid = threadIdx.x;
    const int head = tid >> 5;
    const int lane = tid & 31;
    const int start = rowptr[n];
    const int deg = rowptr[n + 1] - start;   // real in-edges; +1 implicit self loop

    float sd[HEADS];
#pragma unroll
    for (int h = 0; h < HEADS; h++) sd[h] = sdst[n * HEADS + h];

    const int CHUNK = 128;
    __shared__ __align__(16) float sp[CHUNK][HEADS];
    __shared__ __align__(16) int sidx[CHUNK];
    __shared__ __align__(16) float wmax[HEADS][HEADS];
    __shared__ __align__(16) float mmax[HEADS];

    float4 acc = make_float4(0.f, 0.f, 0.f, 0.f);
    float z = 0.f;
    const size_t rowstride = HEADS * 128;
    const int coloff = head * 128 + lane * 4;

    if (deg < CHUNK) {
        // ---- fast path: one global pass over edges ----
        const int len = deg + 1;
        float ml[HEADS];
#pragma unroll
        for (int h = 0; h < HEADS; h++) ml[h] = -1e30f;
        for (int i = tid; i < len; i += T) {
            int s = (i == deg) ? n : esrc[start + i];
            sidx[i] = s;
#pragma unroll
            for (int h = 0; h < HEADS; h++) {
                float e = ssrc[s * HEADS + h] + sd[h];
                e = e > 0.f ? e : 0.2f * e;
                sp[i][h] = e;
                ml[h] = fmaxf(ml[h], e);
            }
        }
#pragma unroll
        for (int h = 0; h < HEADS; h++)
#pragma unroll
            for (int off = 16; off; off >>= 1)
                ml[h] = fmaxf(ml[h], __shfl_xor_sync(0xffffffffu, ml[h], off));

        float mAll[HEADS];
        if (HEADS > 1) {
            if (lane == 0) {
#pragma unroll
                for (int h = 0; h < HEADS; h++) wmax[head][h] = ml[h];
            }
            __syncthreads();
            if (tid < HEADS) {
                float m = wmax[0][tid];
#pragma unroll
                for (int w = 1; w < HEADS; w++) m = fmaxf(m, wmax[w][tid]);
                mmax[tid] = m;
            }
            __syncthreads();
#pragma unroll
            for (int h = 0; h < HEADS; h++) mAll[h] = mmax[h];
        } else {
            mAll[0] = ml[0];
            __syncthreads();   // sp/sidx visibility across the (single) warp's peers
        }

        // exp in smem (same i-partition as the writes)
        for (int i = tid; i < len; i += T) {
#pragma unroll
            for (int h = 0; h < HEADS; h++)
                sp[i][h] = __expf(sp[i][h] - mAll[h]);
        }
        __syncthreads();

        for (int j = 0; j < len; j++) {
            float p = sp[j][head];
            z += p;
            int s = sidx[j];
            const uint2 raw = *(const uint2*)(hlin + (size_t)s * rowstride + coloff);
            __half2 h0 = *(const __half2*)&raw.x;
            __half2 h1 = *(const __half2*)&raw.y;
            float2 f0 = __half22float2(h0);
            float2 f1 = __half22float2(h1);
            acc.x += p * f0.x;
            acc.y += p * f0.y;
            acc.z += p * f1.x;
            acc.w += p * f1.y;
        }
    } else {
        // ---- slow path: exact R10 two-pass ----
        float ml[HEADS];
#pragma unroll
        for (int h = 0; h < HEADS; h++) ml[h] = -1e30f;
        for (int i = tid; i <= deg; i += T) {
            int s = (i == deg) ? n : esrc[start + i];
#pragma unroll
            for (int h = 0; h < HEADS; h++) {
                float e = ssrc[s * HEADS + h] + sd[h];
                e = e > 0.f ? e : 0.2f * e;
                ml[h] = fmaxf(ml[h], e);
            }
        }
#pragma unroll
        for (int h = 0; h < HEADS; h++)
#pragma unroll
            for (int off = 16; off; off >>= 1)
                ml[h] = fmaxf(ml[h], __shfl_xor_sync(0xffffffffu, ml[h], off));

        float mAll[HEADS];
        if (HEADS > 1) {
            if (lane == 0) {
#pragma unroll
                for (int h = 0; h < HEADS; h++) wmax[head][h] = ml[h];
            }
            __syncthreads();
            if (tid < HEADS) {
                float m = wmax[0][tid];
#pragma unroll
                for (int w = 1; w < HEADS; w++) m = fmaxf(m, wmax[w][tid]);
                mmax[tid] = m;
            }
            __syncthreads();
#pragma unroll
            for (int h = 0; h < HEADS; h++) mAll[h] = mmax[h];
        } else {
            mAll[0] = ml[0];
        }

        for (int base = 0; base <= deg; base += CHUNK) {
            int len = min(CHUNK, deg + 1 - base);
            for (int i = tid; i < len; i += T) {
                int s = (base + i == deg) ? n : esrc[start + base + i];
                sidx[i] = s;
#pragma unroll
                for (int h = 0; h < HEADS; h++) {
                    float e = ssrc[s * HEADS + h] + sd[h];
                    e = e > 0.f ? e : 0.2f * e;
                    sp[i][h] = __expf(e - mAll[h]);
                }
            }
            __syncthreads();
            for (int j = 0; j < len; j++) {
                float p = sp[j][head];
                z += p;
                int s = sidx[j];
                const uint2 raw = *(const uint2*)(hlin + (size_t)s * rowstride + coloff);
                __half2 h0 = *(const __half2*)&raw.x;
                __half2 h1 = *(const __half2*)&raw.y;
                float2 f0 = __half22float2(h0);
                float2 f1 = __half22float2(h1);
                acc.x += p * f0.x;
                acc.y += p * f0.y;
                acc.z += p * f1.x;
                acc.w += p * f1.y;
            }
            __syncthreads();
        }
    }

    float inv = 1.f / (z + 1e-16f);
    acc.x *= inv; acc.y *= inv; acc.z *= inv; acc.w *= inv;

    if (HEADS == 1) {
        float v[4] = {acc.x, acc.y, acc.z, acc.w};
#pragma unroll
        for (int k = 0; k < 4; k++) {
            int c = lane * 4 + k;
            outf[(size_t)n * 128 + c] = v[k] + bias[c];
        }
    } else {
        __shared__ __align__(16) float hb[HEADS * 128];
        *(float4*)&hb[head * 128 + lane * 4] = acc;
        __syncthreads();
        if (tid < 32) {
            float v[4];
#pragma unroll
            for (int k = 0; k < 4; k++) {
                int c = tid * 4 + k;
                float s = 0.f;
#pragma unroll
                for (int h = 0; h < HEADS; h++) s += hb[h * 128 + c];
                float w = s * (1.f / HEADS) + bias[c];
                if (ELUBN) {
                    w = w > 0.f ? w : (__expf(w) - 1.f);                       // ELU
                    w = (w - rm[c]) * rsqrtf(rv[c] + 1e-5f) * gam[c] + bet[c]; // BN eval
                }
                v[k] = w;
            }
            __half2 o[2] = {__floats2half2_rn(v[0], v[1]), __floats2half2_rn(v[2], v[3])};
            *(uint2*)(outh + (size_t)n * 128 + tid * 4) = *(uint2*)o;
        }
    }
}

// ---------------- pooling ----------------
__global__ void pool_partial(const float* __restrict__ f, const int* __restrict__ batch,
                             float* __restrict__ tot, float* __restrict__ cnt)
{
    int n0 = blockIdx.x * 256;
    int c = threadIdx.x;
    if (n0 >= NN) return;
    int cur = batch[n0];
    float acc = 0.f;
    int lc = 0;
    for (int i = 0; i < 256; i++) {
        int n = n0 + i;
        if (n >= NN) break;
        int g = batch[n];
        if (g != cur) {
            atomicAdd(&tot[cur * 128 + c], acc);
            if (c == 0) atomicAdd(&cnt[cur], (float)lc);
            acc = 0.f; lc = 0; cur = g;
        }
        acc += f[(size_t)n * 128 + c];
        lc++;
    }
    if (lc) {
        atomicAdd(&tot[cur * 128 + c], acc);
        if (c == 0) atomicAdd(&cnt[cur], (float)lc);
    }
}

__global__ void pool_final(const float* __restrict__ tot, const float* __restrict__ cnt,
                           float* __restrict__ out)
{
    int g = blockIdx.x, c = threadIdx.x;
    out[g * 128 + c] = tot[g * 128 + c] / fmaxf(cnt[g], 1.f);
}

// ---------------- host orchestration ----------------
extern "C" void kernel_launch(void* const* d_in, const int* in_sizes, int n_in,
                              void* d_out, int out_size)
{
    const float* x    = (const float*)d_in[0];
    const int*   src  = (const int*)d_in[1];
    const int*   dst  = (const int*)d_in[2];
    const int*   batch= (const int*)d_in[3];
    const float* W1   = (const float*)d_in[4];
    const float* as1  = (const float*)d_in[5];
    const float* ad1  = (const float*)d_in[6];
    const float* b1   = (const float*)d_in[7];
    const float* gm1  = (const float*)d_in[8];
    const float* be1  = (const float*)d_in[9];
    const float* m1   = (const float*)d_in[10];
    const float* v1   = (const float*)d_in[11];
    const float* W2   = (const float*)d_in[12];
    const float* as2  = (const float*)d_in[13];
    const float* ad2  = (const float*)d_in[14];
    const float* b2   = (const float*)d_in[15];
    const float* gm2  = (const float*)d_in[16];
    const float* be2  = (const float*)d_in[17];
    const float* m2   = (const float*)d_in[18];
    const float* v2   = (const float*)d_in[19];
    const float* W3   = (const float*)d_in[20];
    const float* as3  = (const float*)d_in[21];
    const float* ad3  = (const float*)d_in[22];
    const float* b3   = (const float*)d_in[23];

    __half *hlinh, *xh, *w1h, *w2h, *w3h, *f1h, *f2h;
    float *f3, *ssrc, *sdst, *tot, *cnt;
    int *rowptr, *cursor, *deg, *esrc, *bsums;
    cudaGetSymbolAddress((void**)&hlinh, g_hlinh);
    cudaGetSymbolAddress((void**)&xh,    g_xh);
    cudaGetSymbolAddress((void**)&w1h,   g_w1h);
    cudaGetSymbolAddress((void**)&w2h,   g_w2h);
    cudaGetSymbolAddress((void**)&w3h,   g_w3h);
    cudaGetSymbolAddress((void**)&f1h,   g_f1h);
    cudaGetSymbolAddress((void**)&f2h,   g_f2h);
    cudaGetSymbolAddress((void**)&f3,    g_f3);
    cudaGetSymbolAddress((void**)&ssrc,  g_ssrc);
    cudaGetSymbolAddress((void**)&sdst,  g_sdst);
    cudaGetSymbolAddress((void**)&rowptr,g_rowptr);
    cudaGetSymbolAddress((void**)&cursor,g_cursor);
    cudaGetSymbolAddress((void**)&deg,   g_deg);
    cudaGetSymbolAddress((void**)&esrc,  g_esrc);
    cudaGetSymbolAddress((void**)&bsums, g_bsums);
    cudaGetSymbolAddress((void**)&tot,   g_tot);
    cudaGetSymbolAddress((void**)&cnt,   g_cnt);

    static cudaStream_t sB = nullptr, sC = nullptr;
    static cudaEvent_t evFork = nullptr, evB = nullptr, evC1 = nullptr, evC2 = nullptr;
    if (!sB) {
        cudaStreamCreateWithFlags(&sB, cudaStreamNonBlocking);
        cudaStreamCreateWithFlags(&sC, cudaStreamNonBlocking);
        cudaEventCreateWithFlags(&evFork, cudaEventDisableTiming);
        cudaEventCreateWithFlags(&evB, cudaEventDisableTiming);
        cudaEventCreateWithFlags(&evC1, cudaEventDisableTiming);
        cudaEventCreateWithFlags(&evC2, cudaEventDisableTiming);
    }

    const int MB = (NN + 127) / 128;  // 313

    // ---- fork ----
    cudaEventRecord(evFork, 0);
    cudaStreamWaitEvent(sB, evFork, 0);
    cudaStreamWaitEvent(sC, evFork, 0);

    // ---- stream B: CSR build ----
    kzero_i<<<(NN + 255) / 256, 256, 0, sB>>>(deg, NN);
    hist_k<<<(EE + 255) / 256, 256, 0, sB>>>(dst, deg);
    scan_block<<<(NN + 1023) / 1024, 1024, 0, sB>>>(deg, rowptr, bsums, NN);
    scan_sums<<<1, 32, 0, sB>>>(bsums, (NN + 1023) / 1024);
    scan_add<<<(NN + 255) / 256, 256, 0, sB>>>(rowptr, cursor, bsums, NN);
    scatter_k<<<(EE + 255) / 256, 256, 0, sB>>>(src, dst, cursor, esrc);
    cudaEventRecord(evB, sB);

    // ---- stream C: weight conversions + pool zeroing ----
    conv_half<<<(DIN * 512 / 8 + 255) / 256, 256, 0, sC>>>(W1, w1h, DIN * 512 / 8);
    cudaEventRecord(evC1, sC);
    conv_half<<<(128 * 512 / 8 + 255) / 256, 256, 0, sC>>>(W2, w2h, 128 * 512 / 8);
    conv_half<<<(128 * 128 / 8 + 255) / 256, 256, 0, sC>>>(W3, w3h, 128 * 128 / 8);
    kzero_pool<<<(GG * 128 + 255) / 256, 256, 0, sC>>>(tot, cnt);
    cudaEventRecord(evC2, sC);

    // ---- main stream ----
    conv_half<<<(NN * DIN / 8 + 255) / 256, 256>>>(x, xh, NN * DIN / 8);
    cudaStreamWaitEvent(0, evC1, 0);
    gemm_h<<<dim3(4, MB), 256>>>(NN, 256, 512, xh, w1h, hlinh, 4, as1, ad1, ssrc, sdst);
    cudaStreamWaitEvent(0, evB, 0);
    gat_agg<4, true><<<NN, 128>>>(hlinh, ssrc, sdst, rowptr, esrc, b1, gm1, be1, m1, v1, f1h, nullptr);

    cudaStreamWaitEvent(0, evC2, 0);
    gemm_h<<<dim3(4, MB), 256>>>(NN, 128, 512, f1h, w2h, hlinh, 4, as2, ad2, ssrc, sdst);
    gat_agg<4, true><<<NN, 128>>>(hlinh, ssrc, sdst, rowptr, esrc, b2, gm2, be2, m2, v2, f2h, nullptr);

    gemm_h<<<dim3(1, MB), 256>>>(NN, 128, 128, f2h, w3h, hlinh, 1, as3, ad3, ssrc, sdst);
    gat_agg<1, false><<<NN, 32>>>(hlinh, ssrc, sdst, rowptr, esrc, b3,
                                  nullptr, nullptr, nullptr, nullptr, nullptr, f3);

    // ---- global mean pool ----
    pool_partial<<<(NN + 255) / 256, 128>>>(f3, batch, tot, cnt);
    pool_final<<<GG, 128>>>(tot, cnt, (float*)d_out);
}

// round 15
// speedup vs baseline: 1.3832x; 1.0013x over previous
#include <cuda_runtime.h>
#include <cuda_fp16.h>
#include <mma.h>
#include <cstdint>

using namespace nvcuda;

// Problem constants (fixed by the dataset)
#define NN 40000
#define EE 400000
#define GG 256
#define DIN 256
#define HH 4

#define MPAD 40064   // 313 * 128, padded rows for unguarded stores

// ---------------- scratch (static device globals; no allocation) ----------------
__device__ __half g_hlinh[(size_t)MPAD * 512];  // GEMM output (half), current layer
__device__ __half g_xh[(size_t)NN * DIN];       // x converted to half
__device__ __half g_w1h[DIN * 512];
__device__ __half g_w2h[128 * 512];
__device__ __half g_w3h[128 * 128];
__device__ __half g_f1h[(size_t)NN * 128];      // layer1 out (half)
__device__ __half g_f2h[(size_t)NN * 128];      // layer2 out (half)
__device__ float  g_ssrc[NN * HH];
__device__ float  g_sdst[NN * HH];
__device__ int    g_rowptr[NN + 1];
__device__ int    g_cursor[NN];
__device__ int    g_deg[NN];
__device__ int    g_esrc[EE];
__device__ int    g_bsums[64];
__device__ float  g_tot[GG * 128];
__device__ float  g_cnt[GG];

// ---------------- utility kernels ----------------
__global__ void kzero_i(int* p, int n) {
    int i = blockIdx.x * blockDim.x + threadIdx.x;
    if (i < n) p[i] = 0;
}
__global__ void kzero_pool(float* tot, float* cnt) {
    int i = blockIdx.x * blockDim.x + threadIdx.x;
    if (i < GG * 128) tot[i] = 0.f;
    if (i < GG) cnt[i] = 0.f;
}
// static per-graph node counts (batch is fixed input)
__global__ void count_batch(const int* __restrict__ batch, float* __restrict__ cnt) {
    int i = blockIdx.x * blockDim.x + threadIdx.x;
    if (i < NN) atomicAdd(&cnt[batch[i]], 1.f);
}

// convert fp32 array to half, 8 elements per thread (n % 8 == 0)
__global__ void conv_half(const float* __restrict__ in, __half* __restrict__ out, int n8) {
    int i = blockIdx.x * blockDim.x + threadIdx.x;
    if (i < n8) {
        float4 a = ((const float4*)in)[2 * i];
        float4 b = ((const float4*)in)[2 * i + 1];
        __half2 h[4];
        h[0] = __floats2half2_rn(a.x, a.y);
        h[1] = __floats2half2_rn(a.z, a.w);
        h[2] = __floats2half2_rn(b.x, b.y);
        h[3] = __floats2half2_rn(b.z, b.w);
        ((uint4*)out)[i] = *(uint4*)h;
    }
}

__global__ void hist_k(const int* __restrict__ dst, int* __restrict__ deg) {
    int e = blockIdx.x * blockDim.x + threadIdx.x;
    if (e < EE) atomicAdd(&deg[dst[e]], 1);
}

__global__ void scan_block(const int* __restrict__ deg, int* __restrict__ rowptr,
                           int* __restrict__ bsums, int n) {
    __shared__ int tmp[1024];
    int i = blockIdx.x * 1024 + threadIdx.x;
    int v = (i < n) ? deg[i] : 0;
    tmp[threadIdx.x] = v;
    __syncthreads();
    for (int off = 1; off < 1024; off <<= 1) {
        int t = (threadIdx.x >= off) ? tmp[threadIdx.x - off] : 0;
        __syncthreads();
        tmp[threadIdx.x] += t;
        __syncthreads();
    }
    if (i < n) rowptr[i] = tmp[threadIdx.x] - v;  // exclusive
    if (threadIdx.x == 1023) bsums[blockIdx.x] = tmp[1023];
}

__global__ void scan_sums(int* bsums, int nb) {
    if (threadIdx.x == 0 && blockIdx.x == 0) {
        int run = 0;
        for (int b = 0; b < nb; b++) { int v = bsums[b]; bsums[b] = run; run += v; }
    }
}

__global__ void scan_add(int* __restrict__ rowptr, int* __restrict__ cursor,
                         const int* __restrict__ bsums, int n) {
    int i = blockIdx.x * blockDim.x + threadIdx.x;
    if (i < n) {
        int v = rowptr[i] + bsums[i >> 10];
        rowptr[i] = v;
        cursor[i] = v;
    }
    if (i == 0) rowptr[n] = EE;
}

__global__ void scatter_k(const int* __restrict__ src, const int* __restrict__ dst,
                          int* __restrict__ cursor, int* __restrict__ esrc) {
    int e = blockIdx.x * blockDim.x + threadIdx.x;
    if (e < EE) {
        int pos = atomicAdd(&cursor[dst[e]], 1);
        esrc[pos] = src[e];
    }
}

// ---------------- FP16 tensor-core GEMM + fused attention-score epilogue ----------
#define GBM 128
#define GBN 128
#define GBK 32
#define ALD 40     // A smem row stride (halfs)
#define BLD 136    // B smem row stride (halfs)
#define AB_BYTES (2 * GBM * ALD * 2 + 2 * GBK * BLD * 2)   // 37888
#define CS_LD 68   // epilogue float staging stride

__global__ __launch_bounds__(256) void gemm_h(int M, int K, int Nc,
    const __half* __restrict__ A, const __half* __restrict__ B, __half* __restrict__ C,
    int heads, const float* __restrict__ asrc, const float* __restrict__ adst,
    float* __restrict__ ssrc, float* __restrict__ sdst)
{
    __shared__ __align__(16) char smem_raw[AB_BYTES];   // reused by epilogue
    __half* Ah = (__half*)smem_raw;                     // [2][GBM*ALD]
    __half* Bh = Ah + 2 * GBM * ALD;                    // [2][GBK*BLD]

    const int tid = threadIdx.x;
    const int warpId = tid >> 5;
    const int warpM = warpId & 3;
    const int warpN = warpId >> 2;
    const int head = blockIdx.x;
    const int blockM = blockIdx.y * GBM;
    const int blockN = head * GBN;

    const unsigned int sA = (unsigned int)__cvta_generic_to_shared(Ah);
    const unsigned int sB = (unsigned int)__cvta_generic_to_shared(Bh);

    wmma::fragment<wmma::accumulator, 16, 16, 16, float> acc[2][4];
#pragma unroll
    for (int i = 0; i < 2; i++)
#pragma unroll
        for (int j = 0; j < 4; j++) wmma::fill_fragment(acc[i][j], 0.f);

    const int nsteps = K / GBK;

    auto stage = [&](int buf, int k0) {
#pragma unroll
        for (int q = 0; q < 2; q++) {
            int c = tid + q * 256;
            int ar = c >> 2, ac = (c & 3) * 8;
            int gr = blockM + ar;
            const __half* gpA = A + (size_t)gr * K + k0 + ac;
            unsigned int saA = sA + (unsigned int)(buf * GBM * ALD + ar * ALD + ac) * 2u;
            int sz = (gr < M) ? 16 : 0;
            asm volatile("cp.async.cg.shared.global [%0], [%1], 16, %2;\n"
                         :: "r"(saA), "l"(gpA), "r"(sz));
            int br = c >> 4, bc = (c & 15) * 8;
            const __half* gpB = B + (size_t)(k0 + br) * Nc + blockN + bc;
            unsigned int saB = sB + (unsigned int)(buf * GBK * BLD + br * BLD + bc) * 2u;
            asm volatile("cp.async.cg.shared.global [%0], [%1], 16;\n"
                         :: "r"(saB), "l"(gpB));
        }
        asm volatile("cp.async.commit_group;\n");
    };

    stage(0, 0);

    for (int s = 0; s < nsteps; s++) {
        const int p = s & 1;
        if (s + 1 < nsteps) {
            stage(1 - p, (s + 1) * GBK);
            asm volatile("cp.async.wait_group 1;\n");
        } else {
            asm volatile("cp.async.wait_group 0;\n");
        }
        __syncthreads();

        const __half* ap = Ah + p * GBM * ALD;
        const __half* bp = Bh + p * GBK * BLD;
#pragma unroll
        for (int kk = 0; kk < GBK; kk += 16) {
            wmma::fragment<wmma::matrix_a, 16, 16, 16, __half, wmma::row_major> af[2];
            wmma::fragment<wmma::matrix_b, 16, 16, 16, __half, wmma::row_major> bf[4];
#pragma unroll
            for (int i = 0; i < 2; i++)
                wmma::load_matrix_sync(af[i], ap + (warpM * 32 + i * 16) * ALD + kk, ALD);
#pragma unroll
            for (int j = 0; j < 4; j++)
                wmma::load_matrix_sync(bf[j], bp + kk * BLD + warpN * 64 + j * 16, BLD);
#pragma unroll
            for (int i = 0; i < 2; i++)
#pragma unroll
                for (int j = 0; j < 4; j++)
                    wmma::mma_sync(acc[i][j], af[i], bf[j], acc[i][j]);
        }
        __syncthreads();
    }

    // fused epilogue: acc -> smem(fp32) -> half C + attention dots
    float* Cs = (float*)smem_raw;            // [128][CS_LD]
    const float* asrc_h = asrc + head * 128;
    const float* adst_h = adst + head * 128;
    const int row = tid >> 1;
    const int cseg = (tid & 1) * 32;
    float ds = 0.f, dd = 0.f;

#pragma unroll
    for (int p = 0; p < 2; p++) {
        if (warpN == p) {
#pragma unroll
            for (int i = 0; i < 2; i++)
#pragma unroll
                for (int j = 0; j < 4; j++)
                    wmma::store_matrix_sync(Cs + (warpM * 32 + i * 16) * CS_LD + j * 16,
                                            acc[i][j], CS_LD, wmma::mem_row_major);
        }
        __syncthreads();

        const float* crow = Cs + row * CS_LD + cseg;
        __half2 hbuf[16];
        int colbase = p * 64 + cseg;
#pragma unroll
        for (int k = 0; k < 32; k += 2) {
            float a0 = crow[k], a1 = crow[k + 1];
            hbuf[k >> 1] = __floats2half2_rn(a0, a1);
            ds += a0 * asrc_h[colbase + k] + a1 * asrc_h[colbase + k + 1];
            dd += a0 * adst_h[colbase + k] + a1 * adst_h[colbase + k + 1];
        }
        uint4* dstp = (uint4*)(C + (size_t)(blockM + row) * Nc + blockN + colbase);
        const uint4* srcv = (const uint4*)hbuf;
        dstp[0] = srcv[0]; dstp[1] = srcv[1]; dstp[2] = srcv[2]; dstp[3] = srcv[3];
        __syncthreads();
    }

    ds += __shfl_xor_sync(0xffffffffu, ds, 1);
    dd += __shfl_xor_sync(0xffffffffu, dd, 1);
    int gr = blockM + row;
    if ((tid & 1) == 0 && gr < M) {
        ssrc[gr * heads + head] = ds;
        sdst[gr * heads + head] = dd;
    }
}

// ---------------- per-dst aggregation (HEADS*32 threads) ------------------------
// Fast path (deg < CHUNK): single global pass (R14). Slow path: two-pass (R10).
// HEADS==1 (layer 3): output is pooled directly — atomicAdd into tot[batch[n]].
template <int HEADS, bool ELUBN>
__global__ void gat_agg(const __half* __restrict__ hlin,
                        const float* __restrict__ ssrc, const float* __restrict__ sdst,
                        const int* __restrict__ rowptr, const int* __restrict__ esrc,
                        const float* __restrict__ bias,
                        const float* __restrict__ gam, const float* __restrict__ bet,
                        const float* __restrict__ rm, const float* __restrict__ rv,
                        __half* __restrict__ outh,
                        const int* __restrict__ batch, float* __restrict__ tot)
{
    const int T = HEADS * 32;
    const int n = blockIdx.x;
    const int tid = threadIdx.x;
    const int head = tid >> 5;
    const int lane = tid & 31;
    const int start = rowptr[n];
    const int deg = rowptr[n + 1] - start;   // real in-edges; +1 implicit self loop

    float sd[HEADS];
#pragma unroll
    for (int h = 0; h < HEADS; h++) sd[h] = sdst[n * HEADS + h];

    const int CHUNK = 128;
    __shared__ __align__(16) float sp[CHUNK][HEADS];
    __shared__ __align__(16) int sidx[CHUNK];
    __shared__ __align__(16) float wmax[HEADS][HEADS];
    __shared__ __align__(16) float mmax[HEADS];

    float4 acc = make_float4(0.f, 0.f, 0.f, 0.f);
    float z = 0.f;
    const size_t rowstride = HEADS * 128;
    const int coloff = head * 128 + lane * 4;

    if (deg < CHUNK) {
        // ---- fast path: one global pass over edges ----
        const int len = deg + 1;
        float ml[HEADS];
#pragma unroll
        for (int h = 0; h < HEADS; h++) ml[h] = -1e30f;
        for (int i = tid; i < len; i += T) {
            int s = (i == deg) ? n : esrc[start + i];
            sidx[i] = s;
#pragma unroll
            for (int h = 0; h < HEADS; h++) {
                float e = ssrc[s * HEADS + h] + sd[h];
                e = e > 0.f ? e : 0.2f * e;
                sp[i][h] = e;
                ml[h] = fmaxf(ml[h], e);
            }
        }
#pragma unroll
        for (int h = 0; h < HEADS; h++)
#pragma unroll
            for (int off = 16; off; off >>= 1)
                ml[h] = fmaxf(ml[h], __shfl_xor_sync(0xffffffffu, ml[h], off));

        float mAll[HEADS];
        if (HEADS > 1) {
            if (lane == 0) {
#pragma unroll
                for (int h = 0; h < HEADS; h++) wmax[head][h] = ml[h];
            }
            __syncthreads();
            if (tid < HEADS) {
                float m = wmax[0][tid];
#pragma unroll
                for (int w = 1; w < HEADS; w++) m = fmaxf(m, wmax[w][tid]);
                mmax[tid] = m;
            }
            __syncthreads();
#pragma unroll
            for (int h = 0; h < HEADS; h++) mAll[h] = mmax[h];
        } else {
            mAll[0] = ml[0];
            __syncthreads();
        }

        for (int i = tid; i < len; i += T) {
#pragma unroll
            for (int h = 0; h < HEADS; h++)
                sp[i][h] = __expf(sp[i][h] - mAll[h]);
        }
        __syncthreads();

        for (int j = 0; j < len; j++) {
            float p = sp[j][head];
            z += p;
            int s = sidx[j];
            const uint2 raw = *(const uint2*)(hlin + (size_t)s * rowstride + coloff);
            __half2 h0 = *(const __half2*)&raw.x;
            __half2 h1 = *(const __half2*)&raw.y;
            float2 f0 = __half22float2(h0);
            float2 f1 = __half22float2(h1);
            acc.x += p * f0.x;
            acc.y += p * f0.y;
            acc.z += p * f1.x;
            acc.w += p * f1.y;
        }
    } else {
        // ---- slow path: exact two-pass ----
        float ml[HEADS];
#pragma unroll
        for (int h = 0; h < HEADS; h++) ml[h] = -1e30f;
        for (int i = tid; i <= deg; i += T) {
            int s = (i == deg) ? n : esrc[start + i];
#pragma unroll
            for (int h = 0; h < HEADS; h++) {
                float e = ssrc[s * HEADS + h] + sd[h];
                e = e > 0.f ? e : 0.2f * e;
                ml[h] = fmaxf(ml[h], e);
            }
        }
#pragma unroll
        for (int h = 0; h < HEADS; h++)
#pragma unroll
            for (int off = 16; off; off >>= 1)
                ml[h] = fmaxf(ml[h], __shfl_xor_sync(0xffffffffu, ml[h], off));

        float mAll[HEADS];
        if (HEADS > 1) {
            if (lane == 0) {
#pragma unroll
                for (int h = 0; h < HEADS; h++) wmax[head][h] = ml[h];
            }
            __syncthreads();
            if (tid < HEADS) {
                float m = wmax[0][tid];
#pragma unroll
                for (int w = 1; w < HEADS; w++) m = fmaxf(m, wmax[w][tid]);
                mmax[tid] = m;
            }
            __syncthreads();
#pragma unroll
            for (int h = 0; h < HEADS; h++) mAll[h] = mmax[h];
        } else {
            mAll[0] = ml[0];
        }

        for (int base = 0; base <= deg; base += CHUNK) {
            int len = min(CHUNK, deg + 1 - base);
            for (int i = tid; i < len; i += T) {
                int s = (base + i == deg) ? n : esrc[start + base + i];
                sidx[i] = s;
#pragma unroll
                for (int h = 0; h < HEADS; h++) {
                    float e = ssrc[s * HEADS + h] + sd[h];
                    e = e > 0.f ? e : 0.2f * e;
                    sp[i][h] = __expf(e - mAll[h]);
                }
            }
            __syncthreads();
            for (int j = 0; j < len; j++) {
                float p = sp[j][head];
                z += p;
                int s = sidx[j];
                const uint2 raw = *(const uint2*)(hlin + (size_t)s * rowstride + coloff);
                __half2 h0 = *(const __half2*)&raw.x;
                __half2 h1 = *(const __half2*)&raw.y;
                float2 f0 = __half22float2(h0);
                float2 f1 = __half22float2(h1);
                acc.x += p * f0.x;
                acc.y += p * f0.y;
                acc.z += p * f1.x;
                acc.w += p * f1.y;
            }
            __syncthreads();
        }
    }

    float inv = 1.f / (z + 1e-16f);
    acc.x *= inv; acc.y *= inv; acc.z *= inv; acc.w *= inv;

    if (HEADS == 1) {
        // fused global pooling: add node's output row into its graph's total
        float* trow = tot + (size_t)batch[n] * 128;
        float v[4] = {acc.x, acc.y, acc.z, acc.w};
#pragma unroll
        for (int k = 0; k < 4; k++) {
            int c = lane * 4 + k;
            atomicAdd(&trow[c], v[k] + bias[c]);
        }
    } else {
        __shared__ __align__(16) float hb[HEADS * 128];
        *(float4*)&hb[head * 128 + lane * 4] = acc;
        __syncthreads();
        if (tid < 32) {
            float v[4];
#pragma unroll
            for (int k = 0; k < 4; k++) {
                int c = tid * 4 + k;
                float s = 0.f;
#pragma unroll
                for (int h = 0; h < HEADS; h++) s += hb[h * 128 + c];
                float w = s * (1.f / HEADS) + bias[c];
                if (ELUBN) {
                    w = w > 0.f ? w : (__expf(w) - 1.f);                       // ELU
                    w = (w - rm[c]) * rsqrtf(rv[c] + 1e-5f) * gam[c] + bet[c]; // BN eval
                }
                v[k] = w;
            }
            __half2 o[2] = {__floats2half2_rn(v[0], v[1]), __floats2half2_rn(v[2], v[3])};
            *(uint2*)(outh + (size_t)n * 128 + tid * 4) = *(uint2*)o;
        }
    }
}

// ---------------- pooling finalize ----------------
__global__ void pool_final(const float* __restrict__ tot, const float* __restrict__ cnt,
                           float* __restrict__ out)
{
    int g = blockIdx.x, c = threadIdx.x;
    out[g * 128 + c] = tot[g * 128 + c] / fmaxf(cnt[g], 1.f);
}

// ---------------- host orchestration ----------------
extern "C" void kernel_launch(void* const* d_in, const int* in_sizes, int n_in,
                              void* d_out, int out_size)
{
    const float* x    = (const float*)d_in[0];
    const int*   src  = (const int*)d_in[1];
    const int*   dst  = (const int*)d_in[2];
    const int*   batch= (const int*)d_in[3];
    const float* W1   = (const float*)d_in[4];
    const float* as1  = (const float*)d_in[5];
    const float* ad1  = (const float*)d_in[6];
    const float* b1   = (const float*)d_in[7];
    const float* gm1  = (const float*)d_in[8];
    const float* be1  = (const float*)d_in[9];
    const float* m1   = (const float*)d_in[10];
    const float* v1   = (const float*)d_in[11];
    const float* W2   = (const float*)d_in[12];
    const float* as2  = (const float*)d_in[13];
    const float* ad2  = (const float*)d_in[14];
    const float* b2   = (const float*)d_in[15];
    const float* gm2  = (const float*)d_in[16];
    const float* be2  = (const float*)d_in[17];
    const float* m2   = (const float*)d_in[18];
    const float* v2   = (const float*)d_in[19];
    const float* W3   = (const float*)d_in[20];
    const float* as3  = (const float*)d_in[21];
    const float* ad3  = (const float*)d_in[22];
    const float* b3   = (const float*)d_in[23];

    __half *hlinh, *xh, *w1h, *w2h, *w3h, *f1h, *f2h;
    float *ssrc, *sdst, *tot, *cnt;
    int *rowptr, *cursor, *deg, *esrc, *bsums;
    cudaGetSymbolAddress((void**)&hlinh, g_hlinh);
    cudaGetSymbolAddress((void**)&xh,    g_xh);
    cudaGetSymbolAddress((void**)&w1h,   g_w1h);
    cudaGetSymbolAddress((void**)&w2h,   g_w2h);
    cudaGetSymbolAddress((void**)&w3h,   g_w3h);
    cudaGetSymbolAddress((void**)&f1h,   g_f1h);
    cudaGetSymbolAddress((void**)&f2h,   g_f2h);
    cudaGetSymbolAddress((void**)&ssrc,  g_ssrc);
    cudaGetSymbolAddress((void**)&sdst,  g_sdst);
    cudaGetSymbolAddress((void**)&rowptr,g_rowptr);
    cudaGetSymbolAddress((void**)&cursor,g_cursor);
    cudaGetSymbolAddress((void**)&deg,   g_deg);
    cudaGetSymbolAddress((void**)&esrc,  g_esrc);
    cudaGetSymbolAddress((void**)&bsums, g_bsums);
    cudaGetSymbolAddress((void**)&tot,   g_tot);
    cudaGetSymbolAddress((void**)&cnt,   g_cnt);

    static cudaStream_t sB = nullptr, sC = nullptr;
    static cudaEvent_t evFork = nullptr, evB = nullptr, evC1 = nullptr, evC2 = nullptr;
    if (!sB) {
        cudaStreamCreateWithFlags(&sB, cudaStreamNonBlocking);
        cudaStreamCreateWithFlags(&sC, cudaStreamNonBlocking);
        cudaEventCreateWithFlags(&evFork, cudaEventDisableTiming);
        cudaEventCreateWithFlags(&evB, cudaEventDisableTiming);
        cudaEventCreateWithFlags(&evC1, cudaEventDisableTiming);
        cudaEventCreateWithFlags(&evC2, cudaEventDisableTiming);
    }

    const int MB = (NN + 127) / 128;  // 313

    // ---- fork ----
    cudaEventRecord(evFork, 0);
    cudaStreamWaitEvent(sB, evFork, 0);
    cudaStreamWaitEvent(sC, evFork, 0);

    // ---- stream B: CSR build ----
    kzero_i<<<(NN + 255) / 256, 256, 0, sB>>>(deg, NN);
    hist_k<<<(EE + 255) / 256, 256, 0, sB>>>(dst, deg);
    scan_block<<<(NN + 1023) / 1024, 1024, 0, sB>>>(deg, rowptr, bsums, NN);
    scan_sums<<<1, 32, 0, sB>>>(bsums, (NN + 1023) / 1024);
    scan_add<<<(NN + 255) / 256, 256, 0, sB>>>(rowptr, cursor, bsums, NN);
    scatter_k<<<(EE + 255) / 256, 256, 0, sB>>>(src, dst, cursor, esrc);
    cudaEventRecord(evB, sB);

    // ---- stream C: weight conversions + pool zero/count ----
    conv_half<<<(DIN * 512 / 8 + 255) / 256, 256, 0, sC>>>(W1, w1h, DIN * 512 / 8);
    cudaEventRecord(evC1, sC);
    conv_half<<<(128 * 512 / 8 + 255) / 256, 256, 0, sC>>>(W2, w2h, 128 * 512 / 8);
    conv_half<<<(128 * 128 / 8 + 255) / 256, 256, 0, sC>>>(W3, w3h, 128 * 128 / 8);
    kzero_pool<<<(GG * 128 + 255) / 256, 256, 0, sC>>>(tot, cnt);
    count_batch<<<(NN + 255) / 256, 256, 0, sC>>>(batch, cnt);
    cudaEventRecord(evC2, sC);

    // ---- main stream ----
    conv_half<<<(NN * DIN / 8 + 255) / 256, 256>>>(x, xh, NN * DIN / 8);
    cudaStreamWaitEvent(0, evC1, 0);
    gemm_h<<<dim3(4, MB), 256>>>(NN, 256, 512, xh, w1h, hlinh, 4, as1, ad1, ssrc, sdst);
    cudaStreamWaitEvent(0, evB, 0);
    gat_agg<4, true><<<NN, 128>>>(hlinh, ssrc, sdst, rowptr, esrc, b1, gm1, be1, m1, v1,
                                  f1h, nullptr, nullptr);

    cudaStreamWaitEvent(0, evC2, 0);
    gemm_h<<<dim3(4, MB), 256>>>(NN, 128, 512, f1h, w2h, hlinh, 4, as2, ad2, ssrc, sdst);
    gat_agg<4, true><<<NN, 128>>>(hlinh, ssrc, sdst, rowptr, esrc, b2, gm2, be2, m2, v2,
                                  f2h, nullptr, nullptr);

    gemm_h<<<dim3(1, MB), 256>>>(NN, 128, 128, f2h, w3h, hlinh, 1, as3, ad3, ssrc, sdst);
    gat_agg<1, false><<<NN, 32>>>(hlinh, ssrc, sdst, rowptr, esrc, b3,
                                  nullptr, nullptr, nullptr, nullptr,
                                  nullptr, batch, tot);

    // ---- finalize pooled means ----
    pool_final<<<GG, 128>>>(tot, cnt, (float*)d_out);
}

// round 16
// speedup vs baseline: 1.3847x; 1.0010x over previous
#include <cuda_runtime.h>
#include <cuda_fp16.h>
#include <mma.h>
#include <cstdint>

using namespace nvcuda;

// Problem constants (fixed by the dataset)
#define NN 40000
#define EE 400000
#define GG 256
#define DIN 256
#define HH 4

#define MPAD 40064   // 313 * 128, padded rows for unguarded stores
#define NCHA 20096   // 157 * 128: chunk-a rows/nodes
#define MBA 157      // chunk-a GEMM y-blocks
#define MBB 156      // chunk-b GEMM y-blocks (rows 20096..40064)

// ---------------- scratch (static device globals; no allocation) ----------------
__device__ __half g_hlinh[(size_t)MPAD * 512];  // GEMM output (half), current layer
__device__ __half g_xh[(size_t)NN * DIN];       // x converted to half
__device__ __half g_w1h[DIN * 512];
__device__ __half g_w2h[128 * 512];
__device__ __half g_w3h[128 * 128];
__device__ __half g_f1h[(size_t)NN * 128];      // layer1 out (half)
__device__ __half g_f2h[(size_t)NN * 128];      // layer2 out (half)
__device__ float  g_ssrc[NN * HH];
__device__ float  g_sdst[NN * HH];
__device__ int    g_rowptr[NN + 1];
__device__ int    g_cursor[NN];
__device__ int    g_deg[NN];
__device__ int    g_esrc[EE];
__device__ int    g_bsums[64];
__device__ float  g_tot[GG * 128];
__device__ float  g_cnt[GG];

// ---------------- utility kernels ----------------
__global__ void kzero_i(int* p, int n) {
    int i = blockIdx.x * blockDim.x + threadIdx.x;
    if (i < n) p[i] = 0;
}
__global__ void kzero_pool(float* tot, float* cnt) {
    int i = blockIdx.x * blockDim.x + threadIdx.x;
    if (i < GG * 128) tot[i] = 0.f;
    if (i < GG) cnt[i] = 0.f;
}
__global__ void count_batch(const int* __restrict__ batch, float* __restrict__ cnt) {
    int i = blockIdx.x * blockDim.x + threadIdx.x;
    if (i < NN) atomicAdd(&cnt[batch[i]], 1.f);
}

// convert fp32 array to half, 8 elements per thread (n % 8 == 0)
__global__ void conv_half(const float* __restrict__ in, __half* __restrict__ out, int n8) {
    int i = blockIdx.x * blockDim.x + threadIdx.x;
    if (i < n8) {
        float4 a = ((const float4*)in)[2 * i];
        float4 b = ((const float4*)in)[2 * i + 1];
        __half2 h[4];
        h[0] = __floats2half2_rn(a.x, a.y);
        h[1] = __floats2half2_rn(a.z, a.w);
        h[2] = __floats2half2_rn(b.x, b.y);
        h[3] = __floats2half2_rn(b.z, b.w);
        ((uint4*)out)[i] = *(uint4*)h;
    }
}

__global__ void hist_k(const int* __restrict__ dst, int* __restrict__ deg) {
    int e = blockIdx.x * blockDim.x + threadIdx.x;
    if (e < EE) atomicAdd(&deg[dst[e]], 1);
}

__global__ void scan_block(const int* __restrict__ deg, int* __restrict__ rowptr,
                           int* __restrict__ bsums, int n) {
    __shared__ int tmp[1024];
    int i = blockIdx.x * 1024 + threadIdx.x;
    int v = (i < n) ? deg[i] : 0;
    tmp[threadIdx.x] = v;
    __syncthreads();
    for (int off = 1; off < 1024; off <<= 1) {
        int t = (threadIdx.x >= off) ? tmp[threadIdx.x - off] : 0;
        __syncthreads();
        tmp[threadIdx.x] += t;
        __syncthreads();
    }
    if (i < n) rowptr[i] = tmp[threadIdx.x] - v;  // exclusive
    if (threadIdx.x == 1023) bsums[blockIdx.x] = tmp[1023];
}

__global__ void scan_sums(int* bsums, int nb) {
    if (threadIdx.x == 0 && blockIdx.x == 0) {
        int run = 0;
        for (int b = 0; b < nb; b++) { int v = bsums[b]; bsums[b] = run; run += v; }
    }
}

__global__ void scan_add(int* __restrict__ rowptr, int* __restrict__ cursor,
                         const int* __restrict__ bsums, int n) {
    int i = blockIdx.x * blockDim.x + threadIdx.x;
    if (i < n) {
        int v = rowptr[i] + bsums[i >> 10];
        rowptr[i] = v;
        cursor[i] = v;
    }
    if (i == 0) rowptr[n] = EE;
}

__global__ void scatter_k(const int* __restrict__ src, const int* __restrict__ dst,
                          int* __restrict__ cursor, int* __restrict__ esrc) {
    int e = blockIdx.x * blockDim.x + threadIdx.x;
    if (e < EE) {
        int pos = atomicAdd(&cursor[dst[e]], 1);
        esrc[pos] = src[e];
    }
}

// ---------------- FP16 tensor-core GEMM + fused attention-score epilogue ----------
#define GBM 128
#define GBN 128
#define GBK 32
#define ALD 40     // A smem row stride (halfs)
#define BLD 136    // B smem row stride (halfs)
#define AB_BYTES (2 * GBM * ALD * 2 + 2 * GBK * BLD * 2)   // 37888
#define CS_LD 68   // epilogue float staging stride

__global__ __launch_bounds__(256) void gemm_h(int M, int K, int Nc,
    const __half* __restrict__ A, const __half* __restrict__ B, __half* __restrict__ C,
    int heads, const float* __restrict__ asrc, const float* __restrict__ adst,
    float* __restrict__ ssrc, float* __restrict__ sdst, int yoff)
{
    __shared__ __align__(16) char smem_raw[AB_BYTES];   // reused by epilogue
    __half* Ah = (__half*)smem_raw;                     // [2][GBM*ALD]
    __half* Bh = Ah + 2 * GBM * ALD;                    // [2][GBK*BLD]

    const int tid = threadIdx.x;
    const int warpId = tid >> 5;
    const int warpM = warpId & 3;
    const int warpN = warpId >> 2;
    const int head = blockIdx.x;
    const int blockM = (yoff + blockIdx.y) * GBM;
    const int blockN = head * GBN;

    const unsigned int sA = (unsigned int)__cvta_generic_to_shared(Ah);
    const unsigned int sB = (unsigned int)__cvta_generic_to_shared(Bh);

    wmma::fragment<wmma::accumulator, 16, 16, 16, float> acc[2][4];
#pragma unroll
    for (int i = 0; i < 2; i++)
#pragma unroll
        for (int j = 0; j < 4; j++) wmma::fill_fragment(acc[i][j], 0.f);

    const int nsteps = K / GBK;

    auto stage = [&](int buf, int k0) {
#pragma unroll
        for (int q = 0; q < 2; q++) {
            int c = tid + q * 256;
            int ar = c >> 2, ac = (c & 3) * 8;
            int gr = blockM + ar;
            const __half* gpA = A + (size_t)gr * K + k0 + ac;
            unsigned int saA = sA + (unsigned int)(buf * GBM * ALD + ar * ALD + ac) * 2u;
            int sz = (gr < M) ? 16 : 0;
            asm volatile("cp.async.cg.shared.global [%0], [%1], 16, %2;\n"
                         :: "r"(saA), "l"(gpA), "r"(sz));
            int br = c >> 4, bc = (c & 15) * 8;
            const __half* gpB = B + (size_t)(k0 + br) * Nc + blockN + bc;
            unsigned int saB = sB + (unsigned int)(buf * GBK * BLD + br * BLD + bc) * 2u;
            asm volatile("cp.async.cg.shared.global [%0], [%1], 16;\n"
                         :: "r"(saB), "l"(gpB));
        }
        asm volatile("cp.async.commit_group;\n");
    };

    stage(0, 0);

    for (int s = 0; s < nsteps; s++) {
        const int p = s & 1;
        if (s + 1 < nsteps) {
            stage(1 - p, (s + 1) * GBK);
            asm volatile("cp.async.wait_group 1;\n");
        } else {
            asm volatile("cp.async.wait_group 0;\n");
        }
        __syncthreads();

        const __half* ap = Ah + p * GBM * ALD;
        const __half* bp = Bh + p * GBK * BLD;
#pragma unroll
        for (int kk = 0; kk < GBK; kk += 16) {
            wmma::fragment<wmma::matrix_a, 16, 16, 16, __half, wmma::row_major> af[2];
            wmma::fragment<wmma::matrix_b, 16, 16, 16, __half, wmma::row_major> bf[4];
#pragma unroll
            for (int i = 0; i < 2; i++)
                wmma::load_matrix_sync(af[i], ap + (warpM * 32 + i * 16) * ALD + kk, ALD);
#pragma unroll
            for (int j = 0; j < 4; j++)
                wmma::load_matrix_sync(bf[j], bp + kk * BLD + warpN * 64 + j * 16, BLD);
#pragma unroll
            for (int i = 0; i < 2; i++)
#pragma unroll
                for (int j = 0; j < 4; j++)
                    wmma::mma_sync(acc[i][j], af[i], bf[j], acc[i][j]);
        }
        __syncthreads();
    }

    // fused epilogue: acc -> smem(fp32) -> half C + attention dots
    float* Cs = (float*)smem_raw;            // [128][CS_LD]
    const float* asrc_h = asrc + head * 128;
    const float* adst_h = adst + head * 128;
    const int row = tid >> 1;
    const int cseg = (tid & 1) * 32;
    float ds = 0.f, dd = 0.f;

#pragma unroll
    for (int p = 0; p < 2; p++) {
        if (warpN == p) {
#pragma unroll
            for (int i = 0; i < 2; i++)
#pragma unroll
                for (int j = 0; j < 4; j++)
                    wmma::store_matrix_sync(Cs + (warpM * 32 + i * 16) * CS_LD + j * 16,
                                            acc[i][j], CS_LD, wmma::mem_row_major);
        }
        __syncthreads();

        const float* crow = Cs + row * CS_LD + cseg;
        __half2 hbuf[16];
        int colbase = p * 64 + cseg;
#pragma unroll
        for (int k = 0; k < 32; k += 2) {
            float a0 = crow[k], a1 = crow[k + 1];
            hbuf[k >> 1] = __floats2half2_rn(a0, a1);
            ds += a0 * asrc_h[colbase + k] + a1 * asrc_h[colbase + k + 1];
            dd += a0 * adst_h[colbase + k] + a1 * adst_h[colbase + k + 1];
        }
        uint4* dstp = (uint4*)(C + (size_t)(blockM + row) * Nc + blockN + colbase);
        const uint4* srcv = (const uint4*)hbuf;
        dstp[0] = srcv[0]; dstp[1] = srcv[1]; dstp[2] = srcv[2]; dstp[3] = srcv[3];
        __syncthreads();
    }

    ds += __shfl_xor_sync(0xffffffffu, ds, 1);
    dd += __shfl_xor_sync(0xffffffffu, dd, 1);
    int gr = blockM + row;
    if ((tid & 1) == 0 && gr < M) {
        ssrc[gr * heads + head] = ds;
        sdst[gr * heads + head] = dd;
    }
}

// ---------------- per-dst aggregation (HEADS*32 threads) ------------------------
// Fast path (deg < CHUNK): single global pass. Slow path: two-pass.
// HEADS==1 (layer 3): output is pooled directly — atomicAdd into tot[batch[n]].
template <int HEADS, bool ELUBN>
__global__ void gat_agg(const __half* __restrict__ hlin,
                        const float* __restrict__ ssrc, const float* __restrict__ sdst,
                        const int* __restrict__ rowptr, const int* __restrict__ esrc,
                        const float* __restrict__ bias,
                        const float* __restrict__ gam, const float* __restrict__ bet,
                        const float* __restrict__ rm, const float* __restrict__ rv,
                        __half* __restrict__ outh,
                        const int* __restrict__ batch, float* __restrict__ tot, int n0)
{
    const int T = HEADS * 32;
    const int n = n0 + blockIdx.x;
    const int tid = threadIdx.x;
    const int head = tid >> 5;
    const int lane = tid & 31;
    const int start = rowptr[n];
    const int deg = rowptr[n + 1] - start;   // real in-edges; +1 implicit self loop

    float sd[HEADS];
#pragma unroll
    for (int h = 0; h < HEADS; h++) sd[h] = sdst[n * HEADS + h];

    const int CHUNK = 128;
    __shared__ __align__(16) float sp[CHUNK][HEADS];
    __shared__ __align__(16) int sidx[CHUNK];
    __shared__ __align__(16) float wmax[HEADS][HEADS];
    __shared__ __align__(16) float mmax[HEADS];

    float4 acc = make_float4(0.f, 0.f, 0.f, 0.f);
    float z = 0.f;
    const size_t rowstride = HEADS * 128;
    const int coloff = head * 128 + lane * 4;

    if (deg < CHUNK) {
        // ---- fast path: one global pass over edges ----
        const int len = deg + 1;
        float ml[HEADS];
#pragma unroll
        for (int h = 0; h < HEADS; h++) ml[h] = -1e30f;
        for (int i = tid; i < len; i += T) {
            int s = (i == deg) ? n : esrc[start + i];
            sidx[i] = s;
#pragma unroll
            for (int h = 0; h < HEADS; h++) {
                float e = ssrc[s * HEADS + h] + sd[h];
                e = e > 0.f ? e : 0.2f * e;
                sp[i][h] = e;
                ml[h] = fmaxf(ml[h], e);
            }
        }
#pragma unroll
        for (int h = 0; h < HEADS; h++)
#pragma unroll
            for (int off = 16; off; off >>= 1)
                ml[h] = fmaxf(ml[h], __shfl_xor_sync(0xffffffffu, ml[h], off));

        float mAll[HEADS];
        if (HEADS > 1) {
            if (lane == 0) {
#pragma unroll
                for (int h = 0; h < HEADS; h++) wmax[head][h] = ml[h];
            }
            __syncthreads();
            if (tid < HEADS) {
                float m = wmax[0][tid];
#pragma unroll
                for (int w = 1; w < HEADS; w++) m = fmaxf(m, wmax[w][tid]);
                mmax[tid] = m;
            }
            __syncthreads();
#pragma unroll
            for (int h = 0; h < HEADS; h++) mAll[h] = mmax[h];
        } else {
            mAll[0] = ml[0];
            __syncthreads();
        }

        for (int i = tid; i < len; i += T) {
#pragma unroll
            for (int h = 0; h < HEADS; h++)
                sp[i][h] = __expf(sp[i][h] - mAll[h]);
        }
        __syncthreads();

        for (int j = 0; j < len; j++) {
            float p = sp[j][head];
            z += p;
            int s = sidx[j];
            const uint2 raw = *(const uint2*)(hlin + (size_t)s * rowstride + coloff);
            __half2 h0 = *(const __half2*)&raw.x;
            __half2 h1 = *(const __half2*)&raw.y;
            float2 f0 = __half22float2(h0);
            float2 f1 = __half22float2(h1);
            acc.x += p * f0.x;
            acc.y += p * f0.y;
            acc.z += p * f1.x;
            acc.w += p * f1.y;
        }
    } else {
        // ---- slow path: exact two-pass ----
        float ml[HEADS];
#pragma unroll
        for (int h = 0; h < HEADS; h++) ml[h] = -1e30f;
        for (int i = tid; i <= deg; i += T) {
            int s = (i == deg) ? n : esrc[start + i];
#pragma unroll
            for (int h = 0; h < HEADS; h++) {
                float e = ssrc[s * HEADS + h] + sd[h];
                e = e > 0.f ? e : 0.2f * e;
                ml[h] = fmaxf(ml[h], e);
            }
        }
#pragma unroll
        for (int h = 0; h < HEADS; h++)
#pragma unroll
            for (int off = 16; off; off >>= 1)
                ml[h] = fmaxf(ml[h], __shfl_xor_sync(0xffffffffu, ml[h], off));

        float mAll[HEADS];
        if (HEADS > 1) {
            if (lane == 0) {
#pragma unroll
                for (int h = 0; h < HEADS; h++) wmax[head][h] = ml[h];
            }
            __syncthreads();
            if (tid < HEADS) {
                float m = wmax[0][tid];
#pragma unroll
                for (int w = 1; w < HEADS; w++) m = fmaxf(m, wmax[w][tid]);
                mmax[tid] = m;
            }
            __syncthreads();
#pragma unroll
            for (int h = 0; h < HEADS; h++) mAll[h] = mmax[h];
        } else {
            mAll[0] = ml[0];
        }

        for (int base = 0; base <= deg; base += CHUNK) {
            int len = min(CHUNK, deg + 1 - base);
            for (int i = tid; i < len; i += T) {
                int s = (base + i == deg) ? n : esrc[start + base + i];
                sidx[i] = s;
#pragma unroll
                for (int h = 0; h < HEADS; h++) {
                    float e = ssrc[s * HEADS + h] + sd[h];
                    e = e > 0.f ? e : 0.2f * e;
                    sp[i][h] = __expf(e - mAll[h]);
                }
            }
            __syncthreads();
            for (int j = 0; j < len; j++) {
                float p = sp[j][head];
                z += p;
                int s = sidx[j];
                const uint2 raw = *(const uint2*)(hlin + (size_t)s * rowstride + coloff);
                __half2 h0 = *(const __half2*)&raw.x;
                __half2 h1 = *(const __half2*)&raw.y;
                float2 f0 = __half22float2(h0);
                float2 f1 = __half22float2(h1);
                acc.x += p * f0.x;
                acc.y += p * f0.y;
                acc.z += p * f1.x;
                acc.w += p * f1.y;
            }
            __syncthreads();
        }
    }

    float inv = 1.f / (z + 1e-16f);
    acc.x *= inv; acc.y *= inv; acc.z *= inv; acc.w *= inv;

    if (HEADS == 1) {
        float* trow = tot + (size_t)batch[n] * 128;
        float v[4] = {acc.x, acc.y, acc.z, acc.w};
#pragma unroll
        for (int k = 0; k < 4; k++) {
            int c = lane * 4 + k;
            atomicAdd(&trow[c], v[k] + bias[c]);
        }
    } else {
        __shared__ __align__(16) float hb[HEADS * 128];
        *(float4*)&hb[head * 128 + lane * 4] = acc;
        __syncthreads();
        if (tid < 32) {
            float v[4];
#pragma unroll
            for (int k = 0; k < 4; k++) {
                int c = tid * 4 + k;
                float s = 0.f;
#pragma unroll
                for (int h = 0; h < HEADS; h++) s += hb[h * 128 + c];
                float w = s * (1.f / HEADS) + bias[c];
                if (ELUBN) {
                    w = w > 0.f ? w : (__expf(w) - 1.f);                       // ELU
                    w = (w - rm[c]) * rsqrtf(rv[c] + 1e-5f) * gam[c] + bet[c]; // BN eval
                }
                v[k] = w;
            }
            __half2 o[2] = {__floats2half2_rn(v[0], v[1]), __floats2half2_rn(v[2], v[3])};
            *(uint2*)(outh + (size_t)n * 128 + tid * 4) = *(uint2*)o;
        }
    }
}

// ---------------- pooling finalize ----------------
__global__ void pool_final(const float* __restrict__ tot, const float* __restrict__ cnt,
                           float* __restrict__ out)
{
    int g = blockIdx.x, c = threadIdx.x;
    out[g * 128 + c] = tot[g * 128 + c] / fmaxf(cnt[g], 1.f);
}

// ---------------- host orchestration ----------------
extern "C" void kernel_launch(void* const* d_in, const int* in_sizes, int n_in,
                              void* d_out, int out_size)
{
    const float* x    = (const float*)d_in[0];
    const int*   src  = (const int*)d_in[1];
    const int*   dst  = (const int*)d_in[2];
    const int*   batch= (const int*)d_in[3];
    const float* W1   = (const float*)d_in[4];
    const float* as1  = (const float*)d_in[5];
    const float* ad1  = (const float*)d_in[6];
    const float* b1   = (const float*)d_in[7];
    const float* gm1  = (const float*)d_in[8];
    const float* be1  = (const float*)d_in[9];
    const float* m1   = (const float*)d_in[10];
    const float* v1   = (const float*)d_in[11];
    const float* W2   = (const float*)d_in[12];
    const float* as2  = (const float*)d_in[13];
    const float* ad2  = (const float*)d_in[14];
    const float* b2   = (const float*)d_in[15];
    const float* gm2  = (const float*)d_in[16];
    const float* be2  = (const float*)d_in[17];
    const float* m2   = (const float*)d_in[18];
    const float* v2   = (const float*)d_in[19];
    const float* W3   = (const float*)d_in[20];
    const float* as3  = (const float*)d_in[21];
    const float* ad3  = (const float*)d_in[22];
    const float* b3   = (const float*)d_in[23];

    __half *hlinh, *xh, *w1h, *w2h, *w3h, *f1h, *f2h;
    float *ssrc, *sdst, *tot, *cnt;
    int *rowptr, *cursor, *deg, *esrc, *bsums;
    cudaGetSymbolAddress((void**)&hlinh, g_hlinh);
    cudaGetSymbolAddress((void**)&xh,    g_xh);
    cudaGetSymbolAddress((void**)&w1h,   g_w1h);
    cudaGetSymbolAddress((void**)&w2h,   g_w2h);
    cudaGetSymbolAddress((void**)&w3h,   g_w3h);
    cudaGetSymbolAddress((void**)&f1h,   g_f1h);
    cudaGetSymbolAddress((void**)&f2h,   g_f2h);
    cudaGetSymbolAddress((void**)&ssrc,  g_ssrc);
    cudaGetSymbolAddress((void**)&sdst,  g_sdst);
    cudaGetSymbolAddress((void**)&rowptr,g_rowptr);
    cudaGetSymbolAddress((void**)&cursor,g_cursor);
    cudaGetSymbolAddress((void**)&deg,   g_deg);
    cudaGetSymbolAddress((void**)&esrc,  g_esrc);
    cudaGetSymbolAddress((void**)&bsums, g_bsums);
    cudaGetSymbolAddress((void**)&tot,   g_tot);
    cudaGetSymbolAddress((void**)&cnt,   g_cnt);

    static cudaStream_t sB = nullptr, sC = nullptr, sD = nullptr;
    static cudaEvent_t evFork = nullptr, evB = nullptr, evC1 = nullptr, evC2 = nullptr;
    static cudaEvent_t evXa = nullptr, evG1a = nullptr, evA1a = nullptr;
    static cudaEvent_t evG2a = nullptr, evA2a = nullptr, evG3a = nullptr;
    if (!sB) {
        cudaStreamCreateWithFlags(&sB, cudaStreamNonBlocking);
        cudaStreamCreateWithFlags(&sC, cudaStreamNonBlocking);
        cudaStreamCreateWithFlags(&sD, cudaStreamNonBlocking);
        cudaEventCreateWithFlags(&evFork, cudaEventDisableTiming);
        cudaEventCreateWithFlags(&evB, cudaEventDisableTiming);
        cudaEventCreateWithFlags(&evC1, cudaEventDisableTiming);
        cudaEventCreateWithFlags(&evC2, cudaEventDisableTiming);
        cudaEventCreateWithFlags(&evXa, cudaEventDisableTiming);
        cudaEventCreateWithFlags(&evG1a, cudaEventDisableTiming);
        cudaEventCreateWithFlags(&evA1a, cudaEventDisableTiming);
        cudaEventCreateWithFlags(&evG2a, cudaEventDisableTiming);
        cudaEventCreateWithFlags(&evA2a, cudaEventDisableTiming);
        cudaEventCreateWithFlags(&evG3a, cudaEventDisableTiming);
    }

    const int NCHB = NN - NCHA;          // 19904 nodes in chunk b
    const int XA8 = NCHA * DIN / 8;      // x chunk-a half8 count
    const int XB8 = (NN - NCHA) * DIN / 8;

    // ---- fork ----
    cudaEventRecord(evFork, 0);
    cudaStreamWaitEvent(sB, evFork, 0);
    cudaStreamWaitEvent(sC, evFork, 0);

    // ---- stream B: CSR build ----
    kzero_i<<<(NN + 255) / 256, 256, 0, sB>>>(deg, NN);
    hist_k<<<(EE + 255) / 256, 256, 0, sB>>>(dst, deg);
    scan_block<<<(NN + 1023) / 1024, 1024, 0, sB>>>(deg, rowptr, bsums, NN);
    scan_sums<<<1, 32, 0, sB>>>(bsums, (NN + 1023) / 1024);
    scan_add<<<(NN + 255) / 256, 256, 0, sB>>>(rowptr, cursor, bsums, NN);
    scatter_k<<<(EE + 255) / 256, 256, 0, sB>>>(src, dst, cursor, esrc);
    cudaEventRecord(evB, sB);

    // ---- stream C: weight conversions + pool zero/count ----
    conv_half<<<(DIN * 512 / 8 + 255) / 256, 256, 0, sC>>>(W1, w1h, DIN * 512 / 8);
    cudaEventRecord(evC1, sC);
    conv_half<<<(128 * 512 / 8 + 255) / 256, 256, 0, sC>>>(W2, w2h, 128 * 512 / 8);
    conv_half<<<(128 * 128 / 8 + 255) / 256, 256, 0, sC>>>(W3, w3h, 128 * 128 / 8);
    kzero_pool<<<(GG * 128 + 255) / 256, 256, 0, sC>>>(tot, cnt);
    count_batch<<<(NN + 255) / 256, 256, 0, sC>>>(batch, cnt);
    cudaEventRecord(evC2, sC);

    // ---- main + sD: chunk-pipelined layers ----
    // x conversion: chunk a, then chunk b (gemm1a on sD overlaps conv_xb)
    conv_half<<<(XA8 + 255) / 256, 256>>>(x, xh, XA8);
    cudaEventRecord(evXa, 0);
    conv_half<<<(XB8 + 255) / 256, 256>>>(x + (size_t)NCHA * DIN, xh + (size_t)NCHA * DIN, XB8);

    cudaStreamWaitEvent(sD, evXa, 0);
    cudaStreamWaitEvent(sD, evC1, 0);
    gemm_h<<<dim3(4, MBA), 256, 0, sD>>>(NN, 256, 512, xh, w1h, hlinh, 4, as1, ad1, ssrc, sdst, 0);
    cudaEventRecord(evG1a, sD);

    cudaStreamWaitEvent(0, evC1, 0);
    gemm_h<<<dim3(4, MBB), 256>>>(NN, 256, 512, xh, w1h, hlinh, 4, as1, ad1, ssrc, sdst, MBA);

    // agg1 needs full gemm1 (scores span all nodes) + CSR
    cudaStreamWaitEvent(0, evG1a, 0);
    cudaStreamWaitEvent(0, evB, 0);
    gat_agg<4, true><<<NCHA, 128>>>(hlinh, ssrc, sdst, rowptr, esrc, b1, gm1, be1, m1, v1,
                                    f1h, nullptr, nullptr, 0);
    cudaEventRecord(evA1a, 0);
    gat_agg<4, true><<<NCHB, 128>>>(hlinh, ssrc, sdst, rowptr, esrc, b1, gm1, be1, m1, v1,
                                    f1h, nullptr, nullptr, NCHA);

    // gemm2a (rows a) on sD overlaps agg1b on main
    cudaStreamWaitEvent(sD, evA1a, 0);
    cudaStreamWaitEvent(sD, evC2, 0);
    gemm_h<<<dim3(4, MBA), 256, 0, sD>>>(NN, 128, 512, f1h, w2h, hlinh, 4, as2, ad2, ssrc, sdst, 0);
    cudaEventRecord(evG2a, sD);

    cudaStreamWaitEvent(0, evC2, 0);
    gemm_h<<<dim3(4, MBB), 256>>>(NN, 128, 512, f1h, w2h, hlinh, 4, as2, ad2, ssrc, sdst, MBA);

    cudaStreamWaitEvent(0, evG2a, 0);
    gat_agg<4, true><<<NCHA, 128>>>(hlinh, ssrc, sdst, rowptr, esrc, b2, gm2, be2, m2, v2,
                                    f2h, nullptr, nullptr, 0);
    cudaEventRecord(evA2a, 0);
    gat_agg<4, true><<<NCHB, 128>>>(hlinh, ssrc, sdst, rowptr, esrc, b2, gm2, be2, m2, v2,
                                    f2h, nullptr, nullptr, NCHA);

    // gemm3a on sD overlaps agg2b on main
    cudaStreamWaitEvent(sD, evA2a, 0);
    gemm_h<<<dim3(1, MBA), 256, 0, sD>>>(NN, 128, 128, f2h, w3h, hlinh, 1, as3, ad3, ssrc, sdst, 0);
    cudaEventRecord(evG3a, sD);

    gemm_h<<<dim3(1, MBB), 256>>>(NN, 128, 128, f2h, w3h, hlinh, 1, as3, ad3, ssrc, sdst, MBA);

    cudaStreamWaitEvent(0, evG3a, 0);
    gat_agg<1, false><<<NN, 32>>>(hlinh, ssrc, sdst, rowptr, esrc, b3,
                                  nullptr, nullptr, nullptr, nullptr,
                                  nullptr, batch, tot, 0);

    // ---- finalize pooled means ----
    pool_final<<<GG, 128>>>(tot, cnt, (float*)d_out);
}